// round 2
// baseline (speedup 1.0000x reference)
#include <cuda_runtime.h>
#include <math.h>

// Hyperbolic conv constants (must match reference)
#define CC    0.05f
#define SQC   0.22360679774997896f          // sqrt(0.05)
#define MINN  1e-15f
#define MAXN  (0.996f / SQC)                // (1 - 4e-3)/sqrt(c)

// Scratch: u = logmap0(pad(x)) laid out [b][j][66*66], 32*64*4356 floats (~35.7MB)
__device__ float g_u[8921088];
__device__ float g_bh[128];                 // expmap0(bias)

__device__ __forceinline__ float artanhc(float z) {
    z = fminf(z, 1.0f - 1e-7f);             // z >= 0 always here
    return 0.5f * (log1pf(z) - log1pf(-z));
}

// ---------------------------------------------------------------------------
// Kernel 0: b_h = expmap0(bias) over the 128-vector
// ---------------------------------------------------------------------------
__global__ void bias_kernel(const float* __restrict__ bias) {
    int t = threadIdx.x;                    // 128 threads
    float v = bias[t];
    float p = v * v;
    #pragma unroll
    for (int o = 16; o > 0; o >>= 1) p += __shfl_xor_sync(0xffffffffu, p, o);
    __shared__ float sm[4];
    if ((t & 31) == 0) sm[t >> 5] = p;
    __syncthreads();
    float s2 = sm[0] + sm[1] + sm[2] + sm[3];
    float bn = fmaxf(sqrtf(s2), MINN);
    float z  = SQC * bn;
    g_bh[t] = tanhf(z) / z * v;
}

// ---------------------------------------------------------------------------
// Kernel 1: u = logmap0(pad(x)) per (b, cin) row. Norm over padded row equals
// norm over the 64x64 interior (pad contributes zeros).
// ---------------------------------------------------------------------------
__global__ __launch_bounds__(256) void u_kernel(const float* __restrict__ x) {
    int row = blockIdx.x;                   // b*64 + j, 2048 blocks
    const float* xr = x + (size_t)row * 4096;
    int t = threadIdx.x;

    float p = 0.0f;
    #pragma unroll
    for (int k = 0; k < 16; k++) { float v = xr[t + (k << 8)]; p += v * v; }
    #pragma unroll
    for (int o = 16; o > 0; o >>= 1) p += __shfl_xor_sync(0xffffffffu, p, o);
    __shared__ float sm[8];
    __shared__ float s_scale;
    if ((t & 31) == 0) sm[t >> 5] = p;
    __syncthreads();
    if (t == 0) {
        float s2 = 0.0f;
        #pragma unroll
        for (int i = 0; i < 8; i++) s2 += sm[i];
        float yn = fmaxf(sqrtf(s2), MINN);
        float z  = SQC * yn;
        s_scale  = artanhc(z) / z;
    }
    __syncthreads();
    float sc = s_scale;

    float* ur = g_u + (size_t)row * 4356;
    for (int idx = t; idx < 4356; idx += 256) {
        int r = idx / 66, c = idx - r * 66;
        float v = 0.0f;
        if (r >= 1 && r <= 64 && c >= 1 && c <= 64)
            v = xr[(r - 1) * 64 + (c - 1)] * sc;
        ur[idx] = v;
    }
}

// ---------------------------------------------------------------------------
// Mobius scan scalar math (done by thread 0, broadcast to block).
// Given row stats sv2=|v|^2, sav=<acc,v>, and running a2=|acc|^2:
// t = project(expmap0(v)); acc' = project(mobius_add(acc, t)).
// Returns (sA, sBt) with acc' = sA*acc + sBt*v; updates a2 = |acc'|^2.
// ---------------------------------------------------------------------------
__device__ __forceinline__ float2 step_scalars(float sv2, float sav, float& a2) {
    float vn  = fmaxf(sqrtf(sv2), MINN);
    float z   = SQC * vn;
    float tau = tanhf(z) / z;                     // expmap0 scale
    float tn  = tau * vn;                          // |t| before project
    float pst = (tn > MAXN) ? (MAXN / tn) : 1.0f;  // project(t)
    float ts  = pst * tau;                         // t = ts * v
    float y2  = ts * ts * sv2;                     // |t|^2
    float xy  = ts * sav;                          // <acc, t>
    float x2  = a2;
    float A   = 1.0f + 2.0f * CC * xy + CC * y2;
    float B   = 1.0f - CC * x2;
    float den = fmaxf(1.0f + 2.0f * CC * xy + CC * CC * x2 * y2, MINN);
    float inv = 1.0f / den;
    float n2  = (A * A * x2 + 2.0f * A * B * xy + B * B * y2) * (inv * inv);
    float n   = fmaxf(sqrtf(n2), MINN);
    float ps  = (n > MAXN) ? (MAXN / n) : 1.0f;    // project(acc')
    a2 = ps * ps * n2;
    return make_float2(A * inv * ps, B * inv * ps * ts);
}

// Final out = project(mobius_add(acc, b_full)), b_full row == bh everywhere.
// Returns (oA, oB): out_p = oA*acc_p + oB.
__device__ __forceinline__ float2 final_scalars(float sacc, float a2, float bh) {
    float y2  = 4096.0f * bh * bh;
    float xy  = bh * sacc;
    float x2  = a2;
    float A   = 1.0f + 2.0f * CC * xy + CC * y2;
    float B   = 1.0f - CC * x2;
    float den = fmaxf(1.0f + 2.0f * CC * xy + CC * CC * x2 * y2, MINN);
    float inv = 1.0f / den;
    float n2  = (A * A * x2 + 2.0f * A * B * xy + B * B * y2) * (inv * inv);
    float n   = fmaxf(sqrtf(n2), MINN);
    float ps  = (n > MAXN) ? (MAXN / n) : 1.0f;
    return make_float2(A * inv * ps, B * inv * ps * bh);
}

// ---------------------------------------------------------------------------
// Kernel 2: one CTA per (b, pair of output channels). 256 threads, each owns
// a 4x4 output tile. acc lives in registers; the 66x66 u tile streams via smem
// (L2-resident, read by 64 CTAs each). Exact scan, 64 iterations.
// ---------------------------------------------------------------------------
__global__ __launch_bounds__(256, 2)
void main_kernel(const float* __restrict__ w, float* __restrict__ out) {
    const int b    = blockIdx.y;
    const int c0   = blockIdx.x * 2;
    const int tid  = threadIdx.x;
    const int ty   = tid >> 4;
    const int tx   = tid & 15;
    const int lane = tid & 31;
    const int wid  = tid >> 5;

    __shared__ float  su[4356];         // 66x66 u tile, stride 66
    __shared__ float  sw[2][64][9];     // weights for both channels
    __shared__ float4 sred[8];
    __shared__ float4 sbc;

    // Preload weights for c0, c0+1 (all 64 input channels)
    for (int i = tid; i < 1152; i += 256) {
        int cc = i / 576, rem = i - cc * 576;
        sw[cc][rem / 9][rem % 9] = w[(size_t)(c0 + cc) * 576 + rem];
    }

    float acc0[16], acc1[16];
    #pragma unroll
    for (int i = 0; i < 16; i++) { acc0[i] = 0.0f; acc1[i] = 0.0f; }
    float a2_0 = 0.0f, a2_1 = 0.0f;     // meaningful on tid 0 only

    float4* su4 = (float4*)su;
    const float* basep = su + (4 * ty) * 66 + 4 * tx;

    for (int j = 0; j < 64; j++) {
        // ---- cooperative u tile load (4356 floats = 1089 float4) ----
        const float4* gu4 = (const float4*)(g_u + (size_t)(b * 64 + j) * 4356);
        #pragma unroll
        for (int k = 0; k < 5; k++) {
            int i = tid + (k << 8);
            if (i < 1089) su4[i] = gu4[i];
        }
        __syncthreads();

        float w0[9], w1[9];
        #pragma unroll
        for (int t2 = 0; t2 < 9; t2++) { w0[t2] = sw[0][j][t2]; w1[t2] = sw[1][j][t2]; }

        // ---- conv: 4x4 outputs per thread, rolling 3-row window ----
        float v0[16], v1[16];
        float rwin[3][6];
        #pragma unroll
        for (int r = 0; r < 3; r++) {
            const float2* p = (const float2*)(basep + r * 66);
            float2 q0 = p[0], q1 = p[1], q2 = p[2];
            rwin[r][0] = q0.x; rwin[r][1] = q0.y; rwin[r][2] = q1.x;
            rwin[r][3] = q1.y; rwin[r][4] = q2.x; rwin[r][5] = q2.y;
        }
        #pragma unroll
        for (int orow = 0; orow < 4; orow++) {
            const int i0 = orow % 3, i1 = (orow + 1) % 3, i2 = (orow + 2) % 3;
            #pragma unroll
            for (int oc = 0; oc < 4; oc++) {
                float a0 = rwin[i0][oc], a1 = rwin[i0][oc + 1], a2r = rwin[i0][oc + 2];
                float b0 = rwin[i1][oc], b1 = rwin[i1][oc + 1], b2 = rwin[i1][oc + 2];
                float e0 = rwin[i2][oc], e1 = rwin[i2][oc + 1], e2 = rwin[i2][oc + 2];
                float s0 = a0*w0[0] + a1*w0[1] + a2r*w0[2]
                         + b0*w0[3] + b1*w0[4] + b2 *w0[5]
                         + e0*w0[6] + e1*w0[7] + e2 *w0[8];
                float s1 = a0*w1[0] + a1*w1[1] + a2r*w1[2]
                         + b0*w1[3] + b1*w1[4] + b2 *w1[5]
                         + e0*w1[6] + e1*w1[7] + e2 *w1[8];
                v0[orow * 4 + oc] = s0;
                v1[orow * 4 + oc] = s1;
            }
            if (orow < 3) {
                const int ir = orow % 3;
                const float2* p = (const float2*)(basep + (orow + 3) * 66);
                float2 q0 = p[0], q1 = p[1], q2 = p[2];
                rwin[ir][0] = q0.x; rwin[ir][1] = q0.y; rwin[ir][2] = q1.x;
                rwin[ir][3] = q1.y; rwin[ir][4] = q2.x; rwin[ir][5] = q2.y;
            }
        }

        // ---- fused reduction: |v|^2 and <acc,v> for both channels ----
        float4 red = make_float4(0.f, 0.f, 0.f, 0.f);
        #pragma unroll
        for (int i = 0; i < 16; i++) {
            red.x += v0[i] * v0[i];  red.y += acc0[i] * v0[i];
            red.z += v1[i] * v1[i];  red.w += acc1[i] * v1[i];
        }
        #pragma unroll
        for (int o = 16; o > 0; o >>= 1) {
            red.x += __shfl_xor_sync(0xffffffffu, red.x, o);
            red.y += __shfl_xor_sync(0xffffffffu, red.y, o);
            red.z += __shfl_xor_sync(0xffffffffu, red.z, o);
            red.w += __shfl_xor_sync(0xffffffffu, red.w, o);
        }
        if (lane == 0) sred[wid] = red;
        __syncthreads();
        if (tid == 0) {
            float4 tt = sred[0];
            #pragma unroll
            for (int i = 1; i < 8; i++) {
                float4 q = sred[i];
                tt.x += q.x; tt.y += q.y; tt.z += q.z; tt.w += q.w;
            }
            float2 s0 = step_scalars(tt.x, tt.y, a2_0);
            float2 s1 = step_scalars(tt.z, tt.w, a2_1);
            sbc = make_float4(s0.x, s0.y, s1.x, s1.y);
        }
        __syncthreads();
        float4 sc = sbc;
        #pragma unroll
        for (int i = 0; i < 16; i++) {
            acc0[i] = sc.x * acc0[i] + sc.y * v0[i];
            acc1[i] = sc.z * acc1[i] + sc.w * v1[i];
        }
    }

    // ---- epilogue: mobius bias add + project ----
    float2 red2 = make_float2(0.f, 0.f);
    #pragma unroll
    for (int i = 0; i < 16; i++) { red2.x += acc0[i]; red2.y += acc1[i]; }
    #pragma unroll
    for (int o = 16; o > 0; o >>= 1) {
        red2.x += __shfl_xor_sync(0xffffffffu, red2.x, o);
        red2.y += __shfl_xor_sync(0xffffffffu, red2.y, o);
    }
    if (lane == 0) sred[wid] = make_float4(red2.x, red2.y, 0.f, 0.f);
    __syncthreads();
    if (tid == 0) {
        float sa0 = 0.f, sa1 = 0.f;
        #pragma unroll
        for (int i = 0; i < 8; i++) { sa0 += sred[i].x; sa1 += sred[i].y; }
        float2 f0 = final_scalars(sa0, a2_0, g_bh[c0]);
        float2 f1 = final_scalars(sa1, a2_1, g_bh[c0 + 1]);
        sbc = make_float4(f0.x, f0.y, f1.x, f1.y);
    }
    __syncthreads();
    float4 fo = sbc;

    float* o0 = out + ((size_t)(b * 128 + c0)) * 4096;
    float* o1 = o0 + 4096;
    #pragma unroll
    for (int orow = 0; orow < 4; orow++) {
        #pragma unroll
        for (int oc = 0; oc < 4; oc++) {
            int pos = (4 * ty + orow) * 64 + 4 * tx + oc;
            int i = orow * 4 + oc;
            o0[pos] = fo.x * acc0[i] + fo.y;
            o1[pos] = fo.z * acc1[i] + fo.w;
        }
    }
}

// ---------------------------------------------------------------------------
extern "C" void kernel_launch(void* const* d_in, const int* in_sizes, int n_in,
                              void* d_out, int out_size) {
    const float* x    = (const float*)d_in[0];   // [32,64,64,64]
    const float* wgt  = (const float*)d_in[1];   // [128,64,3,3]
    const float* bias = (const float*)d_in[2];   // [128]
    float* out = (float*)d_out;                  // [32,128,64,64]

    bias_kernel<<<1, 128>>>(bias);
    u_kernel<<<2048, 256>>>(x);
    dim3 grid(64, 32);                           // (cout/2, bs)
    main_kernel<<<grid, 256>>>(wgt, out);
}

// round 4
// speedup vs baseline: 1.0068x; 1.0068x over previous
#include <cuda_runtime.h>
#include <math.h>

// Hyperbolic conv constants (must match reference)
#define CC    0.05f
#define SQC   0.22360679774997896f          // sqrt(0.05)
#define MINN  1e-15f
#define MAXN  (0.996f / SQC)                // (1 - 4e-3)/sqrt(c)

typedef unsigned long long u64;

// Scratch: u = logmap0(pad(x)) laid out [b][j][66*66], 32*64*4356 floats (~35.7MB)
__device__ float g_u[8921088];
__device__ float g_bh[128];                 // expmap0(bias)

// ---------------------------------------------------------------------------
// packed f32x2 helpers (Blackwell dual-FP32 path, FFMA2 in SASS)
// ---------------------------------------------------------------------------
__device__ __forceinline__ u64 pk(float a, float b) {
    u64 r;
    asm("mov.b64 %0, {%1, %2};" : "=l"(r)
        : "r"(__float_as_uint(a)), "r"(__float_as_uint(b)));
    return r;
}
__device__ __forceinline__ float2 unpk(u64 v) {
    unsigned lo, hi;
    asm("mov.b64 {%0, %1}, %2;" : "=r"(lo), "=r"(hi) : "l"(v));
    return make_float2(__uint_as_float(lo), __uint_as_float(hi));
}
__device__ __forceinline__ u64 fma2(u64 a, u64 b, u64 c) {
    u64 d;
    asm("fma.rn.f32x2 %0, %1, %2, %3;" : "=l"(d) : "l"(a), "l"(b), "l"(c));
    return d;
}
__device__ __forceinline__ u64 mul2(u64 a, u64 b) {
    u64 d;
    asm("mul.rn.f32x2 %0, %1, %2;" : "=l"(d) : "l"(a), "l"(b));
    return d;
}

__device__ __forceinline__ float artanhc(float z) {
    z = fminf(z, 1.0f - 1e-7f);             // z >= 0 always here
    return 0.5f * (log1pf(z) - log1pf(-z));
}

// ---------------------------------------------------------------------------
// Kernel 0: b_h = expmap0(bias) over the 128-vector
// ---------------------------------------------------------------------------
__global__ void bias_kernel(const float* __restrict__ bias) {
    int t = threadIdx.x;                    // 128 threads
    float v = bias[t];
    float p = v * v;
    #pragma unroll
    for (int o = 16; o > 0; o >>= 1) p += __shfl_xor_sync(0xffffffffu, p, o);
    __shared__ float sm[4];
    if ((t & 31) == 0) sm[t >> 5] = p;
    __syncthreads();
    float s2 = sm[0] + sm[1] + sm[2] + sm[3];
    float bn = fmaxf(sqrtf(s2), MINN);
    float z  = SQC * bn;
    g_bh[t] = tanhf(z) / z * v;
}

// ---------------------------------------------------------------------------
// Kernel 1: u = logmap0(pad(x)) per (b, cin) row.
// ---------------------------------------------------------------------------
__global__ __launch_bounds__(256) void u_kernel(const float* __restrict__ x) {
    int row = blockIdx.x;                   // b*64 + j, 2048 blocks
    const float* xr = x + (size_t)row * 4096;
    int t = threadIdx.x;

    float p = 0.0f;
    #pragma unroll
    for (int k = 0; k < 16; k++) { float v = xr[t + (k << 8)]; p += v * v; }
    #pragma unroll
    for (int o = 16; o > 0; o >>= 1) p += __shfl_xor_sync(0xffffffffu, p, o);
    __shared__ float sm[8];
    __shared__ float s_scale;
    if ((t & 31) == 0) sm[t >> 5] = p;
    __syncthreads();
    if (t == 0) {
        float s2 = 0.0f;
        #pragma unroll
        for (int i = 0; i < 8; i++) s2 += sm[i];
        float yn = fmaxf(sqrtf(s2), MINN);
        float z  = SQC * yn;
        s_scale  = artanhc(z) / z;
    }
    __syncthreads();
    float sc = s_scale;

    float* ur = g_u + (size_t)row * 4356;
    for (int idx = t; idx < 4356; idx += 256) {
        int r = idx / 66, c = idx - r * 66;
        float v = 0.0f;
        if (r >= 1 && r <= 64 && c >= 1 && c <= 64)
            v = xr[(r - 1) * 64 + (c - 1)] * sc;
        ur[idx] = v;
    }
}

// ---------------------------------------------------------------------------
// Mobius scan scalar math. Computed redundantly by every thread (deterministic).
// ---------------------------------------------------------------------------
__device__ __forceinline__ float2 step_scalars(float sv2, float sav, float& a2) {
    float vn  = fmaxf(sqrtf(sv2), MINN);
    float z   = SQC * vn;
    float tau = tanhf(z) / z;
    float tn  = tau * vn;
    float pst = (tn > MAXN) ? (MAXN / tn) : 1.0f;
    float ts  = pst * tau;
    float y2  = ts * ts * sv2;
    float xy  = ts * sav;
    float x2  = a2;
    float A   = 1.0f + 2.0f * CC * xy + CC * y2;
    float B   = 1.0f - CC * x2;
    float den = fmaxf(1.0f + 2.0f * CC * xy + CC * CC * x2 * y2, MINN);
    float inv = 1.0f / den;
    float n2  = (A * A * x2 + 2.0f * A * B * xy + B * B * y2) * (inv * inv);
    float n   = fmaxf(sqrtf(n2), MINN);
    float ps  = (n > MAXN) ? (MAXN / n) : 1.0f;
    a2 = ps * ps * n2;
    return make_float2(A * inv * ps, B * inv * ps * ts);
}

__device__ __forceinline__ float2 final_scalars(float sacc, float a2, float bh) {
    float y2  = 4096.0f * bh * bh;
    float xy  = bh * sacc;
    float x2  = a2;
    float A   = 1.0f + 2.0f * CC * xy + CC * y2;
    float B   = 1.0f - CC * x2;
    float den = fmaxf(1.0f + 2.0f * CC * xy + CC * CC * x2 * y2, MINN);
    float inv = 1.0f / den;
    float n2  = (A * A * x2 + 2.0f * A * B * xy + B * B * y2) * (inv * inv);
    float n   = fmaxf(sqrtf(n2), MINN);
    float ps  = (n > MAXN) ? (MAXN / n) : 1.0f;
    return make_float2(A * inv * ps, B * inv * ps * bh);
}

// load one 6-wide window row as 5 overlapping f32x2 pairs
__device__ __forceinline__ void loadrow(const float* p, u64* row) {
    const float2* q = (const float2*)p;
    float2 q0 = q[0], q1 = q[1], q2 = q[2];
    row[0] = pk(q0.x, q0.y);
    row[1] = pk(q0.y, q1.x);
    row[2] = pk(q1.x, q1.y);
    row[3] = pk(q1.y, q2.x);
    row[4] = pk(q2.x, q2.y);
}

// ---------------------------------------------------------------------------
// Kernel 2: one CTA per (b, pair of output channels). 256 threads, 4x4 outputs
// each, output columns packed in f32x2 lane pairs. Double-buffered u tile,
// ONE barrier per scan step, scalars computed redundantly per-thread.
// ---------------------------------------------------------------------------
__global__ __launch_bounds__(256, 2)
void main_kernel(const float* __restrict__ w, float* __restrict__ out) {
    const int b    = blockIdx.y;
    const int c0   = blockIdx.x * 2;
    const int tid  = threadIdx.x;
    const int ty   = tid >> 4;
    const int tx   = tid & 15;
    const int lane = tid & 31;
    const int wid  = tid >> 5;

    __shared__ float  su[2 * 4356];     // double-buffered 66x66 tile
    __shared__ u64    swp[2][576];      // weights pre-duplicated: (w,w) pairs
    __shared__ float4 sred[2][8];

    // Preload duplicated weights + tile 0
    for (int i = tid; i < 1152; i += 256) {
        int cc = i / 576, rem = i - cc * 576;
        float wv = w[(size_t)(c0 + cc) * 576 + rem];
        swp[cc][rem] = pk(wv, wv);
    }
    {
        const float4* g0 = (const float4*)(g_u + (size_t)(b * 64) * 4356);
        float4* s0 = (float4*)su;
        #pragma unroll
        for (int k = 0; k < 5; k++) {
            int i = tid + (k << 8);
            if (i < 1089) s0[i] = g0[i];
        }
    }
    __syncthreads();

    // acc packed: lane pair = (output col 2p, 2p+1); index [orow*2+p]
    u64 acc0[8], acc1[8];
    #pragma unroll
    for (int i = 0; i < 8; i++) { acc0[i] = 0ull; acc1[i] = 0ull; }
    float a2_0 = 0.0f, a2_1 = 0.0f;     // redundant per-thread, deterministic

    const int baseoff = (4 * ty) * 66 + 4 * tx;

    for (int j = 0; j < 64; j++) {
        const int cur = j & 1;
        // ---- prefetch next tile into the other buffer ----
        if (j < 63) {
            const float4* gn = (const float4*)(g_u + (size_t)(b * 64 + j + 1) * 4356);
            float4* sn = (float4*)(su + (cur ^ 1) * 4356);
            #pragma unroll
            for (int k = 0; k < 5; k++) {
                int i = tid + (k << 8);
                if (i < 1089) sn[i] = gn[i];
            }
        }

        const float* basep = su + cur * 4356 + baseoff;
        const u64* w0 = &swp[0][j * 9];
        const u64* w1 = &swp[1][j * 9];

        // ---- conv: rolling 3-row window of packed pairs ----
        u64 v0[8], v1[8];
        u64 rwin[3][5];
        #pragma unroll
        for (int r = 0; r < 3; r++) loadrow(basep + r * 66, rwin[r]);

        #pragma unroll
        for (int orow = 0; orow < 4; orow++) {
            const int i0 = orow % 3, i1 = (orow + 1) % 3, i2 = (orow + 2) % 3;
            u64 s00 = 0ull, s01 = 0ull, s10 = 0ull, s11 = 0ull;
            const int ridx[3] = {i0, i1, i2};
            #pragma unroll
            for (int r = 0; r < 3; r++) {
                const u64* rw = rwin[ridx[r]];
                #pragma unroll
                for (int k = 0; k < 3; k++) {
                    u64 wa = w0[r * 3 + k];
                    u64 wb = w1[r * 3 + k];
                    s00 = fma2(rw[k],     wa, s00);
                    s01 = fma2(rw[2 + k], wa, s01);
                    s10 = fma2(rw[k],     wb, s10);
                    s11 = fma2(rw[2 + k], wb, s11);
                }
            }
            v0[orow * 2]     = s00;
            v0[orow * 2 + 1] = s01;
            v1[orow * 2]     = s10;
            v1[orow * 2 + 1] = s11;
            if (orow < 3) loadrow(basep + (orow + 3) * 66, rwin[orow % 3]);
        }

        // ---- fused packed reduction: |v|^2 and <acc,v> per channel ----
        u64 sq0 = 0ull, av0 = 0ull, sq1 = 0ull, av1 = 0ull;
        #pragma unroll
        for (int i = 0; i < 8; i++) {
            sq0 = fma2(v0[i], v0[i], sq0);
            av0 = fma2(acc0[i], v0[i], av0);
            sq1 = fma2(v1[i], v1[i], sq1);
            av1 = fma2(acc1[i], v1[i], av1);
        }
        float2 pa = unpk(sq0), pb = unpk(av0), pc = unpk(sq1), pd = unpk(av1);
        float4 red = make_float4(pa.x + pa.y, pb.x + pb.y, pc.x + pc.y, pd.x + pd.y);
        #pragma unroll
        for (int o = 16; o > 0; o >>= 1) {
            red.x += __shfl_xor_sync(0xffffffffu, red.x, o);
            red.y += __shfl_xor_sync(0xffffffffu, red.y, o);
            red.z += __shfl_xor_sync(0xffffffffu, red.z, o);
            red.w += __shfl_xor_sync(0xffffffffu, red.w, o);
        }
        if (lane == 0) sred[cur][wid] = red;
        __syncthreads();                      // single barrier per scan step

        float4 tt = sred[cur][0];
        #pragma unroll
        for (int i = 1; i < 8; i++) {
            float4 q = sred[cur][i];
            tt.x += q.x; tt.y += q.y; tt.z += q.z; tt.w += q.w;
        }
        float2 s0 = step_scalars(tt.x, tt.y, a2_0);
        float2 s1 = step_scalars(tt.z, tt.w, a2_1);
        u64 A0 = pk(s0.x, s0.x), B0 = pk(s0.y, s0.y);
        u64 A1 = pk(s1.x, s1.x), B1 = pk(s1.y, s1.y);
        #pragma unroll
        for (int i = 0; i < 8; i++) {
            acc0[i] = fma2(A0, acc0[i], mul2(B0, v0[i]));
            acc1[i] = fma2(A1, acc1[i], mul2(B1, v1[i]));
        }
    }

    // ---- epilogue: mobius bias add + project ----
    float sa0 = 0.0f, sa1 = 0.0f;
    #pragma unroll
    for (int i = 0; i < 8; i++) {
        float2 p0 = unpk(acc0[i]); sa0 += p0.x + p0.y;
        float2 p1 = unpk(acc1[i]); sa1 += p1.x + p1.y;
    }
    #pragma unroll
    for (int o = 16; o > 0; o >>= 1) {
        sa0 += __shfl_xor_sync(0xffffffffu, sa0, o);
        sa1 += __shfl_xor_sync(0xffffffffu, sa1, o);
    }
    if (lane == 0) sred[0][wid] = make_float4(sa0, sa1, 0.f, 0.f);
    __syncthreads();
    float t0 = 0.0f, t1 = 0.0f;
    #pragma unroll
    for (int i = 0; i < 8; i++) { t0 += sred[0][i].x; t1 += sred[0][i].y; }
    float2 f0 = final_scalars(t0, a2_0, g_bh[c0]);
    float2 f1 = final_scalars(t1, a2_1, g_bh[c0 + 1]);
    u64 FA0 = pk(f0.x, f0.x), FB0 = pk(f0.y, f0.y);
    u64 FA1 = pk(f1.x, f1.x), FB1 = pk(f1.y, f1.y);

    u64* o0 = (u64*)(out + ((size_t)(b * 128 + c0)) * 4096);
    u64* o1 = o0 + 2048;
    #pragma unroll
    for (int orow = 0; orow < 4; orow++) {
        #pragma unroll
        for (int p = 0; p < 2; p++) {
            int pos = (4 * ty + orow) * 32 + 2 * tx + p;   // in float2 units
            o0[pos] = fma2(FA0, acc0[orow * 2 + p], FB0);
            o1[pos] = fma2(FA1, acc1[orow * 2 + p], FB1);
        }
    }
}

// ---------------------------------------------------------------------------
extern "C" void kernel_launch(void* const* d_in, const int* in_sizes, int n_in,
                              void* d_out, int out_size) {
    const float* x    = (const float*)d_in[0];   // [32,64,64,64]
    const float* wgt  = (const float*)d_in[1];   // [128,64,3,3]
    const float* bias = (const float*)d_in[2];   // [128]
    float* out = (float*)d_out;                  // [32,128,64,64]

    bias_kernel<<<1, 128>>>(bias);
    u_kernel<<<2048, 256>>>(x);
    dim3 grid(64, 32);                           // (cout/2, bs)
    main_kernel<<<grid, 256>>>(wgt, out);
}

// round 5
// speedup vs baseline: 1.1743x; 1.1663x over previous
#include <cuda_runtime.h>
#include <math.h>

// Hyperbolic conv constants (must match reference)
#define CC    0.05f
#define SQC   0.22360679774997896f          // sqrt(0.05)
#define MINN  1e-15f
#define MAXN  (0.996f / SQC)                // (1 - 4e-3)/sqrt(c)

typedef unsigned long long u64;

// Scratch: u = logmap0(pad(x)) laid out [b][j][66*66], 32*64*4356 floats (~35.7MB)
__device__ float g_u[8921088];
__device__ float g_bh[128];                 // expmap0(bias)

// ---------------------------------------------------------------------------
// packed f32x2 + fast-approx helpers
// ---------------------------------------------------------------------------
__device__ __forceinline__ u64 pk(float a, float b) {
    u64 r;
    asm("mov.b64 %0, {%1, %2};" : "=l"(r)
        : "r"(__float_as_uint(a)), "r"(__float_as_uint(b)));
    return r;
}
__device__ __forceinline__ float2 unpk(u64 v) {
    unsigned lo, hi;
    asm("mov.b64 {%0, %1}, %2;" : "=r"(lo), "=r"(hi) : "l"(v));
    return make_float2(__uint_as_float(lo), __uint_as_float(hi));
}
__device__ __forceinline__ u64 fma2(u64 a, u64 b, u64 c) {
    u64 d;
    asm("fma.rn.f32x2 %0, %1, %2, %3;" : "=l"(d) : "l"(a), "l"(b), "l"(c));
    return d;
}
__device__ __forceinline__ float fexp2(float x){ float r; asm("ex2.approx.f32 %0, %1;" : "=f"(r) : "f"(x)); return r; }
__device__ __forceinline__ float frcp (float x){ float r; asm("rcp.approx.f32 %0, %1;" : "=f"(r) : "f"(x)); return r; }
__device__ __forceinline__ float frsq (float x){ float r; asm("rsqrt.approx.f32 %0, %1;" : "=f"(r) : "f"(x)); return r; }

__device__ __forceinline__ float artanhc(float z) {
    z = fminf(z, 1.0f - 1e-7f);             // z >= 0 always here
    return 0.5f * (log1pf(z) - log1pf(-z));
}

// tanh(z)/z, z>=0.  Small z: Pade-free Taylor (avoids exp cancellation);
// larger z: exp2-based. Selected, both deterministic.
__device__ __forceinline__ float tanh_over_z(float z) {
    float z2 = z * z;
    float poly = 1.0f + z2 * (-0.33333334f + z2 * (0.13333334f - z2 * 0.053968254f));
    float t  = fexp2(z * 2.8853901f);       // e^{2z}
    float ex = (t - 1.0f) * frcp((t + 1.0f) * z);
    return (z < 0.25f) ? poly : ex;
}

// ---------------------------------------------------------------------------
// Kernel 0: b_h = expmap0(bias) (precise; runs once, negligible)
// ---------------------------------------------------------------------------
__global__ void bias_kernel(const float* __restrict__ bias) {
    int t = threadIdx.x;                    // 128 threads
    float v = bias[t];
    float p = v * v;
    #pragma unroll
    for (int o = 16; o > 0; o >>= 1) p += __shfl_xor_sync(0xffffffffu, p, o);
    __shared__ float sm[4];
    if ((t & 31) == 0) sm[t >> 5] = p;
    __syncthreads();
    float s2 = sm[0] + sm[1] + sm[2] + sm[3];
    float bn = fmaxf(sqrtf(s2), MINN);
    float z  = SQC * bn;
    g_bh[t] = tanhf(z) / z * v;
}

// ---------------------------------------------------------------------------
// Kernel 1: u = logmap0(pad(x)) per (b, cin) row (precise)
// ---------------------------------------------------------------------------
__global__ __launch_bounds__(256) void u_kernel(const float* __restrict__ x) {
    int row = blockIdx.x;                   // b*64 + j, 2048 blocks
    const float* xr = x + (size_t)row * 4096;
    int t = threadIdx.x;

    float p = 0.0f;
    #pragma unroll
    for (int k = 0; k < 16; k++) { float v = xr[t + (k << 8)]; p += v * v; }
    #pragma unroll
    for (int o = 16; o > 0; o >>= 1) p += __shfl_xor_sync(0xffffffffu, p, o);
    __shared__ float sm[8];
    __shared__ float s_scale;
    if ((t & 31) == 0) sm[t >> 5] = p;
    __syncthreads();
    if (t == 0) {
        float s2 = 0.0f;
        #pragma unroll
        for (int i = 0; i < 8; i++) s2 += sm[i];
        float yn = fmaxf(sqrtf(s2), MINN);
        float z  = SQC * yn;
        s_scale  = artanhc(z) / z;
    }
    __syncthreads();
    float sc = s_scale;

    float* ur = g_u + (size_t)row * 4356;
    for (int idx = t; idx < 4356; idx += 256) {
        int r = idx / 66, c = idx - r * 66;
        float v = 0.0f;
        if (r >= 1 && r <= 64 && c >= 1 && c <= 64)
            v = xr[(r - 1) * 64 + (c - 1)] * sc;
        ur[idx] = v;
    }
}

// ---------------------------------------------------------------------------
// Mobius scan scalar math (fast approx, redundant per thread, deterministic).
// acc is represented as P*q.  qv = <q,v>.  Returns (sA, sBt); updates a2.
// ---------------------------------------------------------------------------
__device__ __forceinline__ float2 step_scalars(float sv2, float qv, float P, float& a2) {
    float sav = P * qv;
    sv2 = fmaxf(sv2, 1e-28f);
    float vn  = sv2 * frsq(sv2);                   // sqrt(sv2)
    float z   = SQC * vn;
    float tau = tanh_over_z(z);
    float tn  = tau * vn;
    float pst = (tn > MAXN) ? (MAXN * frcp(tn)) : 1.0f;
    float ts  = pst * tau;
    float y2  = ts * ts * sv2;
    float xy  = ts * sav;
    float x2  = a2;
    float A   = 1.0f + 2.0f * CC * xy + CC * y2;
    float B   = 1.0f - CC * x2;
    float den = fmaxf(1.0f + 2.0f * CC * xy + CC * CC * x2 * y2, MINN);
    float inv = frcp(den);
    float n2  = (A * A * x2 + 2.0f * A * B * xy + B * B * y2) * (inv * inv);
    float n2c = fmaxf(n2, 1e-28f);
    float n   = n2c * frsq(n2c);
    float ps  = (n > MAXN) ? (MAXN * frcp(n)) : 1.0f;
    a2 = ps * ps * n2;
    return make_float2(A * inv * ps, B * inv * ps * ts);
}

__device__ __forceinline__ float2 final_scalars(float sacc, float a2, float bh) {
    float y2  = 4096.0f * bh * bh;
    float xy  = bh * sacc;
    float x2  = a2;
    float A   = 1.0f + 2.0f * CC * xy + CC * y2;
    float B   = 1.0f - CC * x2;
    float den = fmaxf(1.0f + 2.0f * CC * xy + CC * CC * x2 * y2, MINN);
    float inv = frcp(den);
    float n2  = (A * A * x2 + 2.0f * A * B * xy + B * B * y2) * (inv * inv);
    float n2c = fmaxf(n2, 1e-28f);
    float n   = n2c * frsq(n2c);
    float ps  = (n > MAXN) ? (MAXN * frcp(n)) : 1.0f;
    return make_float2(A * inv * ps, B * inv * ps * bh);
}

// load one 6-wide window row as 5 overlapping f32x2 pairs
__device__ __forceinline__ void loadrow(const float* p, u64* row) {
    const float2* q = (const float2*)p;
    float2 q0 = q[0], q1 = q[1], q2 = q[2];
    row[0] = pk(q0.x, q0.y);
    row[1] = pk(q0.y, q1.x);
    row[2] = pk(q1.x, q1.y);
    row[3] = pk(q1.y, q2.x);
    row[4] = pk(q2.x, q2.y);
}

// ---------------------------------------------------------------------------
// Kernel 2: one CTA per (b, channel pair).  256 threads, 4x4 outputs each,
// columns packed f32x2.  Double-buffered tile, single barrier per scan step,
// prefetch LDG issued INTO the post-barrier scalar bubble, STS at next top.
// ---------------------------------------------------------------------------
__global__ __launch_bounds__(256, 2)
void main_kernel(const float* __restrict__ w, float* __restrict__ out) {
    const int b    = blockIdx.y;
    const int c0   = blockIdx.x * 2;
    const int tid  = threadIdx.x;
    const int ty   = tid >> 4;
    const int tx   = tid & 15;
    const int lane = tid & 31;
    const int wid  = tid >> 5;

    __shared__ float  su[2 * 4356];     // double-buffered 66x66 tile
    __shared__ u64    swp[2][576];      // weights pre-duplicated (w,w)
    __shared__ float4 sred[2][8];

    for (int i = tid; i < 1152; i += 256) {
        int cc = i / 576, rem = i - cc * 576;
        float wv = w[(size_t)(c0 + cc) * 576 + rem];
        swp[cc][rem] = pk(wv, wv);
    }
    // tile 0 -> buf0 (smem), tile 1 -> pf registers
    {
        const float4* g0 = (const float4*)(g_u + (size_t)(b * 64) * 4356);
        float4* s0 = (float4*)su;
        #pragma unroll
        for (int k = 0; k < 5; k++) {
            int i = tid + (k << 8);
            if (i < 1089) s0[i] = g0[i];
        }
    }
    float4 pf0, pf1, pf2, pf3, pf4;
    {
        const float4* g1 = (const float4*)(g_u + (size_t)(b * 64 + 1) * 4356);
        pf0 = g1[tid]; pf1 = g1[tid + 256]; pf2 = g1[tid + 512]; pf3 = g1[tid + 768];
        pf4 = (tid + 1024 < 1089) ? g1[tid + 1024] : make_float4(0.f, 0.f, 0.f, 0.f);
    }
    __syncthreads();

    u64 q0a[8], q1a[8];                 // acc = P * q, packed col pairs
    #pragma unroll
    for (int i = 0; i < 8; i++) { q0a[i] = 0ull; q1a[i] = 0ull; }
    float a2_0 = 0.0f, a2_1 = 0.0f, P0 = 1.0f, P1 = 1.0f;

    const int baseoff = (4 * ty) * 66 + 4 * tx;

    for (int j = 0; j < 64; j++) {
        const int cur = j & 1;
        // ---- store prefetched tile j+1 into the other buffer ----
        if (j < 63) {
            float4* sn = (float4*)(su + (cur ^ 1) * 4356);
            sn[tid] = pf0; sn[tid + 256] = pf1; sn[tid + 512] = pf2; sn[tid + 768] = pf3;
            if (tid + 1024 < 1089) sn[tid + 1024] = pf4;
        }

        const float* basep = su + cur * 4356 + baseoff;
        const u64* wp0 = &swp[0][j * 9];
        const u64* wp1 = &swp[1][j * 9];

        // ---- conv: rolling 3-row window; weights read from smem (broadcast) ----
        u64 v0[8], v1[8];
        u64 rwin[3][5];
        #pragma unroll
        for (int r = 0; r < 3; r++) loadrow(basep + r * 66, rwin[r]);

        #pragma unroll
        for (int orow = 0; orow < 4; orow++) {
            u64 s00 = 0ull, s01 = 0ull, s10 = 0ull, s11 = 0ull;
            #pragma unroll
            for (int r = 0; r < 3; r++) {
                const u64* rw = rwin[(orow + r) % 3];
                #pragma unroll
                for (int k = 0; k < 3; k++) {
                    u64 wa = wp0[r * 3 + k];
                    u64 wb = wp1[r * 3 + k];
                    s00 = fma2(rw[k],     wa, s00);
                    s01 = fma2(rw[2 + k], wa, s01);
                    s10 = fma2(rw[k],     wb, s10);
                    s11 = fma2(rw[2 + k], wb, s11);
                }
            }
            v0[orow * 2]     = s00;
            v0[orow * 2 + 1] = s01;
            v1[orow * 2]     = s10;
            v1[orow * 2 + 1] = s11;
            if (orow < 3) loadrow(basep + (orow + 3) * 66, rwin[orow % 3]);
        }

        // ---- fused packed reduction: |v|^2 and <q,v> per channel ----
        u64 sq0 = 0ull, av0 = 0ull, sq1 = 0ull, av1 = 0ull;
        #pragma unroll
        for (int i = 0; i < 8; i++) {
            sq0 = fma2(v0[i], v0[i], sq0);
            av0 = fma2(q0a[i], v0[i], av0);
            sq1 = fma2(v1[i], v1[i], sq1);
            av1 = fma2(q1a[i], v1[i], av1);
        }
        float2 pa = unpk(sq0), pb = unpk(av0), pc = unpk(sq1), pd = unpk(av1);
        float4 red = make_float4(pa.x + pa.y, pb.x + pb.y, pc.x + pc.y, pd.x + pd.y);
        #pragma unroll
        for (int o = 16; o > 0; o >>= 1) {
            red.x += __shfl_xor_sync(0xffffffffu, red.x, o);
            red.y += __shfl_xor_sync(0xffffffffu, red.y, o);
            red.z += __shfl_xor_sync(0xffffffffu, red.z, o);
            red.w += __shfl_xor_sync(0xffffffffu, red.w, o);
        }
        if (lane == 0) sred[cur][wid] = red;
        __syncthreads();                      // single barrier per scan step

        // ---- prefetch tile j+2 into registers (fills the scalar bubble) ----
        if (j < 62) {
            const float4* gn = (const float4*)(g_u + (size_t)(b * 64 + j + 2) * 4356);
            pf0 = gn[tid]; pf1 = gn[tid + 256]; pf2 = gn[tid + 512]; pf3 = gn[tid + 768];
            if (tid + 1024 < 1089) pf4 = gn[tid + 1024];
        }

        float4 tt = sred[cur][0];
        #pragma unroll
        for (int i = 1; i < 8; i++) {
            float4 qq = sred[cur][i];
            tt.x += qq.x; tt.y += qq.y; tt.z += qq.z; tt.w += qq.w;
        }
        float2 s0 = step_scalars(tt.x, tt.y, P0, a2_0);
        float2 s1 = step_scalars(tt.z, tt.w, P1, a2_1);
        P0 *= s0.x;  float qc0 = s0.y * frcp(P0);
        P1 *= s1.x;  float qc1 = s1.y * frcp(P1);
        u64 QC0 = pk(qc0, qc0), QC1 = pk(qc1, qc1);
        #pragma unroll
        for (int i = 0; i < 8; i++) {
            q0a[i] = fma2(QC0, v0[i], q0a[i]);
            q1a[i] = fma2(QC1, v1[i], q1a[i]);
        }
    }

    // ---- epilogue: mobius bias add + project (acc = P*q) ----
    float sa0 = 0.0f, sa1 = 0.0f;
    #pragma unroll
    for (int i = 0; i < 8; i++) {
        float2 p0 = unpk(q0a[i]); sa0 += p0.x + p0.y;
        float2 p1 = unpk(q1a[i]); sa1 += p1.x + p1.y;
    }
    #pragma unroll
    for (int o = 16; o > 0; o >>= 1) {
        sa0 += __shfl_xor_sync(0xffffffffu, sa0, o);
        sa1 += __shfl_xor_sync(0xffffffffu, sa1, o);
    }
    if (lane == 0) sred[0][wid] = make_float4(sa0, sa1, 0.f, 0.f);
    __syncthreads();
    float t0 = 0.0f, t1 = 0.0f;
    #pragma unroll
    for (int i = 0; i < 8; i++) { t0 += sred[0][i].x; t1 += sred[0][i].y; }
    float2 f0 = final_scalars(P0 * t0, a2_0, g_bh[c0]);
    float2 f1 = final_scalars(P1 * t1, a2_1, g_bh[c0 + 1]);
    float fx0 = f0.x * P0, fx1 = f1.x * P1;
    u64 FA0 = pk(fx0, fx0), FB0 = pk(f0.y, f0.y);
    u64 FA1 = pk(fx1, fx1), FB1 = pk(f1.y, f1.y);

    u64* o0 = (u64*)(out + ((size_t)(b * 128 + c0)) * 4096);
    u64* o1 = o0 + 2048;
    #pragma unroll
    for (int orow = 0; orow < 4; orow++) {
        #pragma unroll
        for (int p = 0; p < 2; p++) {
            int pos = (4 * ty + orow) * 32 + 2 * tx + p;   // in float2 units
            o0[pos] = fma2(FA0, q0a[orow * 2 + p], FB0);
            o1[pos] = fma2(FA1, q1a[orow * 2 + p], FB1);
        }
    }
}

// ---------------------------------------------------------------------------
extern "C" void kernel_launch(void* const* d_in, const int* in_sizes, int n_in,
                              void* d_out, int out_size) {
    const float* x    = (const float*)d_in[0];   // [32,64,64,64]
    const float* wgt  = (const float*)d_in[1];   // [128,64,3,3]
    const float* bias = (const float*)d_in[2];   // [128]
    float* out = (float*)d_out;                  // [32,128,64,64]

    bias_kernel<<<1, 128>>>(bias);
    u_kernel<<<2048, 256>>>(x);
    dim3 grid(64, 32);                           // (cout/2, bs)
    main_kernel<<<grid, 256>>>(wgt, out);
}

// round 6
// speedup vs baseline: 1.2118x; 1.0319x over previous
#include <cuda_runtime.h>
#include <math.h>

// Hyperbolic conv constants (must match reference)
#define CC    0.05f
#define SQC   0.22360679774997896f          // sqrt(0.05)
#define MINN  1e-15f
#define MAXN  (0.996f / SQC)                // (1 - 4e-3)/sqrt(c)

typedef unsigned long long u64;

// u tile stride padded to 68 floats (272B = 17*16B) so every row is 16B aligned
#define TW    68
#define TSZ   (66 * TW)                     // 4488 floats per tile
#define TSZ4  (TSZ / 4)                     // 1122 float4

// Scratch: u = logmap0(pad(x)), [b][j][66*68], 32*64*4488 floats (~36.8MB)
__device__ float g_u[9191424];
__device__ float g_bh[128];                 // expmap0(bias)

// ---------------------------------------------------------------------------
// packed f32x2 + fast-approx + cp.async helpers
// ---------------------------------------------------------------------------
__device__ __forceinline__ u64 pk(float a, float b) {
    u64 r;
    asm("mov.b64 %0, {%1, %2};" : "=l"(r)
        : "r"(__float_as_uint(a)), "r"(__float_as_uint(b)));
    return r;
}
__device__ __forceinline__ float2 unpk(u64 v) {
    unsigned lo, hi;
    asm("mov.b64 {%0, %1}, %2;" : "=r"(lo), "=r"(hi) : "l"(v));
    return make_float2(__uint_as_float(lo), __uint_as_float(hi));
}
__device__ __forceinline__ u64 fma2(u64 a, u64 b, u64 c) {
    u64 d;
    asm("fma.rn.f32x2 %0, %1, %2, %3;" : "=l"(d) : "l"(a), "l"(b), "l"(c));
    return d;
}
__device__ __forceinline__ float fexp2(float x){ float r; asm("ex2.approx.f32 %0, %1;" : "=f"(r) : "f"(x)); return r; }
__device__ __forceinline__ float frcp (float x){ float r; asm("rcp.approx.f32 %0, %1;" : "=f"(r) : "f"(x)); return r; }
__device__ __forceinline__ float frsq (float x){ float r; asm("rsqrt.approx.f32 %0, %1;" : "=f"(r) : "f"(x)); return r; }

__device__ __forceinline__ void cpasync16(unsigned saddr, const void* g) {
    asm volatile("cp.async.cg.shared.global [%0], [%1], 16;" :: "r"(saddr), "l"(g));
}
#define CP_COMMIT() asm volatile("cp.async.commit_group;")
#define CP_WAIT0()  asm volatile("cp.async.wait_group 0;")

__device__ __forceinline__ float artanhc(float z) {
    z = fminf(z, 1.0f - 1e-7f);             // z >= 0 always here
    return 0.5f * (log1pf(z) - log1pf(-z));
}

// tanh(z)/z, z>=0. Small z: Taylor (avoids cancellation); larger: exp2 path.
__device__ __forceinline__ float tanh_over_z(float z) {
    float z2 = z * z;
    float poly = 1.0f + z2 * (-0.33333334f + z2 * (0.13333334f - z2 * 0.053968254f));
    float t  = fexp2(z * 2.8853901f);       // e^{2z}
    float ex = (t - 1.0f) * frcp((t + 1.0f) * z);
    return (z < 0.25f) ? poly : ex;
}

// ---------------------------------------------------------------------------
// Kernel 0: b_h = expmap0(bias) (precise; runs once, negligible)
// ---------------------------------------------------------------------------
__global__ void bias_kernel(const float* __restrict__ bias) {
    int t = threadIdx.x;                    // 128 threads
    float v = bias[t];
    float p = v * v;
    #pragma unroll
    for (int o = 16; o > 0; o >>= 1) p += __shfl_xor_sync(0xffffffffu, p, o);
    __shared__ float sm[4];
    if ((t & 31) == 0) sm[t >> 5] = p;
    __syncthreads();
    float s2 = sm[0] + sm[1] + sm[2] + sm[3];
    float bn = fmaxf(sqrtf(s2), MINN);
    float z  = SQC * bn;
    g_bh[t] = tanhf(z) / z * v;
}

// ---------------------------------------------------------------------------
// Kernel 1: u = logmap0(pad(x)) per (b, cin) row (precise), stride-68 layout
// ---------------------------------------------------------------------------
__global__ __launch_bounds__(256) void u_kernel(const float* __restrict__ x) {
    int row = blockIdx.x;                   // b*64 + j, 2048 blocks
    const float* xr = x + (size_t)row * 4096;
    int t = threadIdx.x;

    float p = 0.0f;
    #pragma unroll
    for (int k = 0; k < 16; k++) { float v = xr[t + (k << 8)]; p += v * v; }
    #pragma unroll
    for (int o = 16; o > 0; o >>= 1) p += __shfl_xor_sync(0xffffffffu, p, o);
    __shared__ float sm[8];
    __shared__ float s_scale;
    if ((t & 31) == 0) sm[t >> 5] = p;
    __syncthreads();
    if (t == 0) {
        float s2 = 0.0f;
        #pragma unroll
        for (int i = 0; i < 8; i++) s2 += sm[i];
        float yn = fmaxf(sqrtf(s2), MINN);
        float z  = SQC * yn;
        s_scale  = artanhc(z) / z;
    }
    __syncthreads();
    float sc = s_scale;

    float* ur = g_u + (size_t)row * TSZ;
    for (int idx = t; idx < TSZ; idx += 256) {
        int r = idx / TW, c = idx - r * TW;
        float v = 0.0f;
        if (r >= 1 && r <= 64 && c >= 1 && c <= 64)
            v = xr[(r - 1) * 64 + (c - 1)] * sc;
        ur[idx] = v;
    }
}

// ---------------------------------------------------------------------------
// Mobius scan scalar math (fast approx, redundant per thread, deterministic).
// acc = P*q.  qv = <q,v>.  Returns (sA, sBt); updates a2.
// ---------------------------------------------------------------------------
__device__ __forceinline__ float2 step_scalars(float sv2, float qv, float P, float& a2) {
    float sav = P * qv;
    sv2 = fmaxf(sv2, 1e-28f);
    float vn  = sv2 * frsq(sv2);                   // sqrt(sv2)
    float z   = SQC * vn;
    float tau = tanh_over_z(z);
    float tn  = tau * vn;
    float pst = (tn > MAXN) ? (MAXN * frcp(tn)) : 1.0f;
    float ts  = pst * tau;
    float y2  = ts * ts * sv2;
    float xy  = ts * sav;
    float x2  = a2;
    float A   = 1.0f + 2.0f * CC * xy + CC * y2;
    float B   = 1.0f - CC * x2;
    float den = fmaxf(1.0f + 2.0f * CC * xy + CC * CC * x2 * y2, MINN);
    float inv = frcp(den);
    float n2  = (A * A * x2 + 2.0f * A * B * xy + B * B * y2) * (inv * inv);
    float n2c = fmaxf(n2, 1e-28f);
    float n   = n2c * frsq(n2c);
    float ps  = (n > MAXN) ? (MAXN * frcp(n)) : 1.0f;
    a2 = ps * ps * n2;
    return make_float2(A * inv * ps, B * inv * ps * ts);
}

__device__ __forceinline__ float2 final_scalars(float sacc, float a2, float bh) {
    float y2  = 4096.0f * bh * bh;
    float xy  = bh * sacc;
    float x2  = a2;
    float A   = 1.0f + 2.0f * CC * xy + CC * y2;
    float B   = 1.0f - CC * x2;
    float den = fmaxf(1.0f + 2.0f * CC * xy + CC * CC * x2 * y2, MINN);
    float inv = frcp(den);
    float n2  = (A * A * x2 + 2.0f * A * B * xy + B * B * y2) * (inv * inv);
    float n2c = fmaxf(n2, 1e-28f);
    float n   = n2c * frsq(n2c);
    float ps  = (n > MAXN) ? (MAXN * frcp(n)) : 1.0f;
    return make_float2(A * inv * ps, B * inv * ps * bh);
}

// load one 6-wide window row (16B-aligned) as 5 overlapping f32x2 pairs
__device__ __forceinline__ void loadrow(const float* p, u64* row) {
    float4 a = *(const float4*)p;           // floats 0-3 (LDS.128)
    float2 b = *(const float2*)(p + 4);     // floats 4-5 (LDS.64)
    row[0] = pk(a.x, a.y);
    row[1] = pk(a.y, a.z);
    row[2] = pk(a.z, a.w);
    row[3] = pk(a.w, b.x);
    row[4] = pk(b.x, b.y);
}

// ---------------------------------------------------------------------------
// Kernel 2: one CTA per (b, channel pair). 256 threads, 4x4 outputs each,
// columns packed f32x2. Double-buffered tile via cp.async (zero data regs),
// single barrier per scan step, MUFU scalar math redundant per thread.
// ---------------------------------------------------------------------------
__global__ __launch_bounds__(256, 2)
void main_kernel(const float* __restrict__ w, float* __restrict__ out) {
    const int b    = blockIdx.y;
    const int c0   = blockIdx.x * 2;
    const int tid  = threadIdx.x;
    const int ty   = tid >> 4;
    const int tx   = tid & 15;
    const int lane = tid & 31;
    const int wid  = tid >> 5;

    __shared__ float  su[2 * TSZ];      // double-buffered 66x68 tile
    __shared__ u64    swp[2][576];      // weights pre-duplicated (w,w)
    __shared__ float4 sred[2][8];

    for (int i = tid; i < 1152; i += 256) {
        int cc = i / 576, rem = i - cc * 576;
        float wv = w[(size_t)(c0 + cc) * 576 + rem];
        swp[cc][rem] = pk(wv, wv);
    }

    const unsigned su_s = (unsigned)__cvta_generic_to_shared(su);
    const float4* gbase = (const float4*)(g_u + (size_t)(b * 64) * TSZ);

    // preload tile 0 into buf0 via cp.async
    #pragma unroll
    for (int k = 0; k < 5; k++) {
        int i = tid + (k << 8);
        if (i < TSZ4) cpasync16(su_s + i * 16, gbase + i);
    }
    CP_COMMIT();
    CP_WAIT0();
    __syncthreads();

    u64 q0a[8], q1a[8];                 // acc = P * q, packed col pairs
    #pragma unroll
    for (int i = 0; i < 8; i++) { q0a[i] = 0ull; q1a[i] = 0ull; }
    float a2_0 = 0.0f, a2_1 = 0.0f, P0 = 1.0f, P1 = 1.0f;

    const int baseoff = (4 * ty) * TW + 4 * tx;

    for (int j = 0; j < 64; j++) {
        const int cur = j & 1;

        // ---- async prefetch tile j+1 into the other buffer (overlaps conv) ----
        if (j < 63) {
            const float4* gn = gbase + (size_t)(j + 1) * TSZ4;
            unsigned sn = su_s + (cur ^ 1) * (TSZ * 4);
            #pragma unroll
            for (int k = 0; k < 5; k++) {
                int i = tid + (k << 8);
                if (i < TSZ4) cpasync16(sn + i * 16, gn + i);
            }
            CP_COMMIT();
        }

        const float* basep = su + cur * TSZ + baseoff;
        const u64* wp0 = &swp[0][j * 9];
        const u64* wp1 = &swp[1][j * 9];

        // ---- conv: rolling 3-row window; weights broadcast from smem ----
        u64 v0[8], v1[8];
        u64 rwin[3][5];
        #pragma unroll
        for (int r = 0; r < 3; r++) loadrow(basep + r * TW, rwin[r]);

        #pragma unroll
        for (int orow = 0; orow < 4; orow++) {
            u64 s00 = 0ull, s01 = 0ull, s10 = 0ull, s11 = 0ull;
            #pragma unroll
            for (int r = 0; r < 3; r++) {
                const u64* rw = rwin[(orow + r) % 3];
                #pragma unroll
                for (int k = 0; k < 3; k++) {
                    u64 wa = wp0[r * 3 + k];
                    u64 wb = wp1[r * 3 + k];
                    s00 = fma2(rw[k],     wa, s00);
                    s01 = fma2(rw[2 + k], wa, s01);
                    s10 = fma2(rw[k],     wb, s10);
                    s11 = fma2(rw[2 + k], wb, s11);
                }
            }
            v0[orow * 2]     = s00;
            v0[orow * 2 + 1] = s01;
            v1[orow * 2]     = s10;
            v1[orow * 2 + 1] = s11;
            if (orow < 3) loadrow(basep + (orow + 3) * TW, rwin[orow % 3]);
        }

        // ---- fused packed reduction: |v|^2 and <q,v> per channel ----
        u64 sq0 = 0ull, av0 = 0ull, sq1 = 0ull, av1 = 0ull;
        #pragma unroll
        for (int i = 0; i < 8; i++) {
            sq0 = fma2(v0[i], v0[i], sq0);
            av0 = fma2(q0a[i], v0[i], av0);
            sq1 = fma2(v1[i], v1[i], sq1);
            av1 = fma2(q1a[i], v1[i], av1);
        }
        float2 pa = unpk(sq0), pb = unpk(av0), pc = unpk(sq1), pd = unpk(av1);
        float4 red = make_float4(pa.x + pa.y, pb.x + pb.y, pc.x + pc.y, pd.x + pd.y);
        #pragma unroll
        for (int o = 16; o > 0; o >>= 1) {
            red.x += __shfl_xor_sync(0xffffffffu, red.x, o);
            red.y += __shfl_xor_sync(0xffffffffu, red.y, o);
            red.z += __shfl_xor_sync(0xffffffffu, red.z, o);
            red.w += __shfl_xor_sync(0xffffffffu, red.w, o);
        }
        if (lane == 0) sred[cur][wid] = red;

        // prefetch must land before the barrier publishes the buffer
        if (j < 63) CP_WAIT0();
        __syncthreads();                      // single barrier per scan step

        float4 tt = sred[cur][0];
        #pragma unroll
        for (int i = 1; i < 8; i++) {
            float4 qq = sred[cur][i];
            tt.x += qq.x; tt.y += qq.y; tt.z += qq.z; tt.w += qq.w;
        }
        float2 s0 = step_scalars(tt.x, tt.y, P0, a2_0);
        float2 s1 = step_scalars(tt.z, tt.w, P1, a2_1);
        P0 *= s0.x;  float qc0 = s0.y * frcp(P0);
        P1 *= s1.x;  float qc1 = s1.y * frcp(P1);
        u64 QC0 = pk(qc0, qc0), QC1 = pk(qc1, qc1);
        #pragma unroll
        for (int i = 0; i < 8; i++) {
            q0a[i] = fma2(QC0, v0[i], q0a[i]);
            q1a[i] = fma2(QC1, v1[i], q1a[i]);
        }
    }

    // ---- epilogue: mobius bias add + project (acc = P*q) ----
    float sa0 = 0.0f, sa1 = 0.0f;
    #pragma unroll
    for (int i = 0; i < 8; i++) {
        float2 p0 = unpk(q0a[i]); sa0 += p0.x + p0.y;
        float2 p1 = unpk(q1a[i]); sa1 += p1.x + p1.y;
    }
    #pragma unroll
    for (int o = 16; o > 0; o >>= 1) {
        sa0 += __shfl_xor_sync(0xffffffffu, sa0, o);
        sa1 += __shfl_xor_sync(0xffffffffu, sa1, o);
    }
    if (lane == 0) sred[0][wid] = make_float4(sa0, sa1, 0.f, 0.f);
    __syncthreads();
    float t0 = 0.0f, t1 = 0.0f;
    #pragma unroll
    for (int i = 0; i < 8; i++) { t0 += sred[0][i].x; t1 += sred[0][i].y; }
    float2 f0 = final_scalars(P0 * t0, a2_0, g_bh[c0]);
    float2 f1 = final_scalars(P1 * t1, a2_1, g_bh[c0 + 1]);
    float fx0 = f0.x * P0, fx1 = f1.x * P1;
    u64 FA0 = pk(fx0, fx0), FB0 = pk(f0.y, f0.y);
    u64 FA1 = pk(fx1, fx1), FB1 = pk(f1.y, f1.y);

    u64* o0 = (u64*)(out + ((size_t)(b * 128 + c0)) * 4096);
    u64* o1 = o0 + 2048;
    #pragma unroll
    for (int orow = 0; orow < 4; orow++) {
        #pragma unroll
        for (int p = 0; p < 2; p++) {
            int pos = (4 * ty + orow) * 32 + 2 * tx + p;   // in float2 units
            o0[pos] = fma2(FA0, q0a[orow * 2 + p], FB0);
            o1[pos] = fma2(FA1, q1a[orow * 2 + p], FB1);
        }
    }
}

// ---------------------------------------------------------------------------
extern "C" void kernel_launch(void* const* d_in, const int* in_sizes, int n_in,
                              void* d_out, int out_size) {
    const float* x    = (const float*)d_in[0];   // [32,64,64,64]
    const float* wgt  = (const float*)d_in[1];   // [128,64,3,3]
    const float* bias = (const float*)d_in[2];   // [128]
    float* out = (float*)d_out;                  // [32,128,64,64]

    bias_kernel<<<1, 128>>>(bias);
    u_kernel<<<2048, 256>>>(x);
    dim3 grid(64, 32);                           // (cout/2, bs)
    main_kernel<<<grid, 256>>>(wgt, out);
}

// round 7
// speedup vs baseline: 1.2210x; 1.0077x over previous
#include <cuda_runtime.h>
#include <math.h>

// Hyperbolic conv constants (must match reference)
#define CC    0.05f
#define SQC   0.22360679774997896f          // sqrt(0.05)
#define MINN  1e-15f
#define MAXN  (0.996f / SQC)                // (1 - 4e-3)/sqrt(c)

typedef unsigned long long u64;

// u tile stride padded to 68 floats (272B = 17*16B) so every row is 16B aligned
#define TW    68
#define TSZ   (66 * TW)                     // 4488 floats per tile
#define TSZ4  (TSZ / 4)                     // 1122 float4

// Scratch: u = logmap0(pad(x)), [b][j][66*68], 32*64*4488 floats (~36.8MB)
__device__ float g_u[9191424];
__device__ float g_bh[128];                 // expmap0(bias)

// ---------------------------------------------------------------------------
// packed f32x2 + fast-approx + cp.async helpers
// ---------------------------------------------------------------------------
__device__ __forceinline__ u64 pk(float a, float b) {
    u64 r;
    asm("mov.b64 %0, {%1, %2};" : "=l"(r)
        : "r"(__float_as_uint(a)), "r"(__float_as_uint(b)));
    return r;
}
__device__ __forceinline__ float2 unpk(u64 v) {
    unsigned lo, hi;
    asm("mov.b64 {%0, %1}, %2;" : "=r"(lo), "=r"(hi) : "l"(v));
    return make_float2(__uint_as_float(lo), __uint_as_float(hi));
}
__device__ __forceinline__ u64 fma2(u64 a, u64 b, u64 c) {
    u64 d;
    asm("fma.rn.f32x2 %0, %1, %2, %3;" : "=l"(d) : "l"(a), "l"(b), "l"(c));
    return d;
}
__device__ __forceinline__ float fexp2(float x){ float r; asm("ex2.approx.f32 %0, %1;" : "=f"(r) : "f"(x)); return r; }
__device__ __forceinline__ float frcp (float x){ float r; asm("rcp.approx.f32 %0, %1;" : "=f"(r) : "f"(x)); return r; }
__device__ __forceinline__ float frsq (float x){ float r; asm("rsqrt.approx.f32 %0, %1;" : "=f"(r) : "f"(x)); return r; }

__device__ __forceinline__ void cpasync16(unsigned saddr, const void* g) {
    asm volatile("cp.async.cg.shared.global [%0], [%1], 16;" :: "r"(saddr), "l"(g));
}
#define CP_COMMIT() asm volatile("cp.async.commit_group;")
#define CP_WAIT0()  asm volatile("cp.async.wait_group 0;")

__device__ __forceinline__ float4 add4(float4 a, float4 b) {
    return make_float4(a.x + b.x, a.y + b.y, a.z + b.z, a.w + b.w);
}

__device__ __forceinline__ float artanhc(float z) {
    z = fminf(z, 1.0f - 1e-7f);             // z >= 0 always here
    return 0.5f * (log1pf(z) - log1pf(-z));
}

// tanh(z)/z, z>=0. Small z: Taylor (avoids cancellation); larger: exp2 path.
__device__ __forceinline__ float tanh_over_z(float z) {
    float z2 = z * z;
    float poly = 1.0f + z2 * (-0.33333334f + z2 * (0.13333334f - z2 * 0.053968254f));
    float t  = fexp2(z * 2.8853901f);       // e^{2z}
    float ex = (t - 1.0f) * frcp((t + 1.0f) * z);
    return (z < 0.25f) ? poly : ex;
}

// ---------------------------------------------------------------------------
// Kernel 1: u = logmap0(pad(x)) per (b, cin) row (precise), stride-68 layout.
// Block 2048 additionally computes b_h = expmap0(bias) (fused so each
// kernel_launch issues exactly 2 launches -> ncu -s 5 lands on main_kernel).
// ---------------------------------------------------------------------------
__global__ __launch_bounds__(256) void u_kernel(const float* __restrict__ x,
                                                const float* __restrict__ bias) {
    int row = blockIdx.x;
    int t = threadIdx.x;

    if (row == 2048) {                      // bias block
        if (t < 128) {
            float v = bias[t];
            float p = v * v;
            #pragma unroll
            for (int o = 16; o > 0; o >>= 1) p += __shfl_xor_sync(0xffffffffu, p, o);
            __shared__ float smb[4];
            if ((t & 31) == 0) smb[t >> 5] = p;
            __syncwarp();
            asm volatile("bar.sync 1, 128;");
            float s2 = smb[0] + smb[1] + smb[2] + smb[3];
            float bn = fmaxf(sqrtf(s2), MINN);
            float z  = SQC * bn;
            g_bh[t] = tanhf(z) / z * v;
        }
        return;
    }

    const float* xr = x + (size_t)row * 4096;

    float p = 0.0f;
    #pragma unroll
    for (int k = 0; k < 16; k++) { float v = xr[t + (k << 8)]; p += v * v; }
    #pragma unroll
    for (int o = 16; o > 0; o >>= 1) p += __shfl_xor_sync(0xffffffffu, p, o);
    __shared__ float sm[8];
    __shared__ float s_scale;
    if ((t & 31) == 0) sm[t >> 5] = p;
    __syncthreads();
    if (t == 0) {
        float s2 = 0.0f;
        #pragma unroll
        for (int i = 0; i < 8; i++) s2 += sm[i];
        float yn = fmaxf(sqrtf(s2), MINN);
        float z  = SQC * yn;
        s_scale  = artanhc(z) / z;
    }
    __syncthreads();
    float sc = s_scale;

    float* ur = g_u + (size_t)row * TSZ;
    for (int idx = t; idx < TSZ; idx += 256) {
        int r = idx / TW, c = idx - r * TW;
        float v = 0.0f;
        if (r >= 1 && r <= 64 && c >= 1 && c <= 64)
            v = xr[(r - 1) * 64 + (c - 1)] * sc;
        ur[idx] = v;
    }
}

// ---------------------------------------------------------------------------
// Mobius scan scalar math (fast approx, redundant per thread, deterministic).
// acc = P*q.  qv = <q,v>.  Returns (sA, sBt); updates a2.
// ---------------------------------------------------------------------------
__device__ __forceinline__ float2 step_scalars(float sv2, float qv, float P, float& a2) {
    float sav = P * qv;
    sv2 = fmaxf(sv2, 1e-28f);
    float vn  = sv2 * frsq(sv2);                   // sqrt(sv2)
    float z   = SQC * vn;
    float tau = tanh_over_z(z);
    float tn  = tau * vn;
    float pst = (tn > MAXN) ? (MAXN * frcp(tn)) : 1.0f;
    float ts  = pst * tau;
    float y2  = ts * ts * sv2;
    float xy  = ts * sav;
    float x2  = a2;
    float A   = 1.0f + 2.0f * CC * xy + CC * y2;
    float B   = 1.0f - CC * x2;
    float den = fmaxf(1.0f + 2.0f * CC * xy + CC * CC * x2 * y2, MINN);
    float inv = frcp(den);
    float n2  = (A * A * x2 + 2.0f * A * B * xy + B * B * y2) * (inv * inv);
    float n2c = fmaxf(n2, 1e-28f);
    float n   = n2c * frsq(n2c);
    float ps  = (n > MAXN) ? (MAXN * frcp(n)) : 1.0f;
    a2 = ps * ps * n2;
    return make_float2(A * inv * ps, B * inv * ps * ts);
}

__device__ __forceinline__ float2 final_scalars(float sacc, float a2, float bh) {
    float y2  = 4096.0f * bh * bh;
    float xy  = bh * sacc;
    float x2  = a2;
    float A   = 1.0f + 2.0f * CC * xy + CC * y2;
    float B   = 1.0f - CC * x2;
    float den = fmaxf(1.0f + 2.0f * CC * xy + CC * CC * x2 * y2, MINN);
    float inv = frcp(den);
    float n2  = (A * A * x2 + 2.0f * A * B * xy + B * B * y2) * (inv * inv);
    float n2c = fmaxf(n2, 1e-28f);
    float n   = n2c * frsq(n2c);
    float ps  = (n > MAXN) ? (MAXN * frcp(n)) : 1.0f;
    return make_float2(A * inv * ps, B * inv * ps * bh);
}

// load one 6-wide window row (16B-aligned) as 5 overlapping f32x2 pairs
__device__ __forceinline__ void loadrow(const float* p, u64* row) {
    float4 a = *(const float4*)p;           // floats 0-3 (LDS.128)
    float2 b = *(const float2*)(p + 4);     // floats 4-5 (LDS.64)
    row[0] = pk(a.x, a.y);
    row[1] = pk(a.y, a.z);
    row[2] = pk(a.z, a.w);
    row[3] = pk(a.w, b.x);
    row[4] = pk(b.x, b.y);
}

// ---------------------------------------------------------------------------
// Kernel 2: one CTA per (b, channel pair). 256 threads, 4x4 outputs each,
// columns packed f32x2. Double-buffered tile via cp.async, single barrier per
// scan step, scalar chain redundant per thread. Loop unrolled x2 so ptxas can
// overlap the MUFU scalar chain of iter j with the conv of iter j+1.
// ---------------------------------------------------------------------------
__global__ __launch_bounds__(256, 2)
void main_kernel(const float* __restrict__ w, float* __restrict__ out) {
    const int b    = blockIdx.y;
    const int c0   = blockIdx.x * 2;
    const int tid  = threadIdx.x;
    const int ty   = tid >> 4;
    const int tx   = tid & 15;
    const int lane = tid & 31;
    const int wid  = tid >> 5;

    __shared__ float  su[2 * TSZ];      // double-buffered 66x68 tile
    __shared__ u64    swp[2][576];      // weights pre-duplicated (w,w)
    __shared__ float4 sred[2][8];

    for (int i = tid; i < 1152; i += 256) {
        int cc = i / 576, rem = i - cc * 576;
        float wv = w[(size_t)(c0 + cc) * 576 + rem];
        swp[cc][rem] = pk(wv, wv);
    }

    const unsigned su_s = (unsigned)__cvta_generic_to_shared(su);
    const float4* gbase = (const float4*)(g_u + (size_t)(b * 64) * TSZ);

    // preload tile 0 into buf0 via cp.async
    #pragma unroll
    for (int k = 0; k < 5; k++) {
        int i = tid + (k << 8);
        if (i < TSZ4) cpasync16(su_s + i * 16, gbase + i);
    }
    CP_COMMIT();
    CP_WAIT0();
    __syncthreads();

    u64 q0a[8], q1a[8];                 // acc = P * q, packed col pairs
    #pragma unroll
    for (int i = 0; i < 8; i++) { q0a[i] = 0ull; q1a[i] = 0ull; }
    float a2_0 = 0.0f, a2_1 = 0.0f, P0 = 1.0f, P1 = 1.0f;

    const int baseoff = (4 * ty) * TW + 4 * tx;

    #pragma unroll 2
    for (int j = 0; j < 64; j++) {
        const int cur = j & 1;

        // ---- async prefetch tile j+1 into the other buffer (overlaps conv) ----
        if (j < 63) {
            const float4* gn = gbase + (size_t)(j + 1) * TSZ4;
            unsigned sn = su_s + (cur ^ 1) * (TSZ * 4);
            #pragma unroll
            for (int k = 0; k < 5; k++) {
                int i = tid + (k << 8);
                if (i < TSZ4) cpasync16(sn + i * 16, gn + i);
            }
            CP_COMMIT();
        }

        const float* basep = su + cur * TSZ + baseoff;
        const u64* wp0 = &swp[0][j * 9];
        const u64* wp1 = &swp[1][j * 9];

        // ---- conv: rolling 3-row window; weights broadcast from smem ----
        u64 v0[8], v1[8];
        u64 rwin[3][5];
        #pragma unroll
        for (int r = 0; r < 3; r++) loadrow(basep + r * TW, rwin[r]);

        #pragma unroll
        for (int orow = 0; orow < 4; orow++) {
            u64 s00 = 0ull, s01 = 0ull, s10 = 0ull, s11 = 0ull;
            #pragma unroll
            for (int r = 0; r < 3; r++) {
                const u64* rw = rwin[(orow + r) % 3];
                #pragma unroll
                for (int k = 0; k < 3; k++) {
                    u64 wa = wp0[r * 3 + k];
                    u64 wb = wp1[r * 3 + k];
                    s00 = fma2(rw[k],     wa, s00);
                    s01 = fma2(rw[2 + k], wa, s01);
                    s10 = fma2(rw[k],     wb, s10);
                    s11 = fma2(rw[2 + k], wb, s11);
                }
            }
            v0[orow * 2]     = s00;
            v0[orow * 2 + 1] = s01;
            v1[orow * 2]     = s10;
            v1[orow * 2 + 1] = s11;
            if (orow < 3) loadrow(basep + (orow + 3) * TW, rwin[orow % 3]);
        }

        // ---- fused packed reduction: |v|^2 and <q,v> per channel ----
        u64 sq0 = 0ull, av0 = 0ull, sq1 = 0ull, av1 = 0ull;
        #pragma unroll
        for (int i = 0; i < 8; i++) {
            sq0 = fma2(v0[i], v0[i], sq0);
            av0 = fma2(q0a[i], v0[i], av0);
            sq1 = fma2(v1[i], v1[i], sq1);
            av1 = fma2(q1a[i], v1[i], av1);
        }
        float2 pa = unpk(sq0), pb = unpk(av0), pc = unpk(sq1), pd = unpk(av1);
        float4 red = make_float4(pa.x + pa.y, pb.x + pb.y, pc.x + pc.y, pd.x + pd.y);
        #pragma unroll
        for (int o = 16; o > 0; o >>= 1) {
            red.x += __shfl_xor_sync(0xffffffffu, red.x, o);
            red.y += __shfl_xor_sync(0xffffffffu, red.y, o);
            red.z += __shfl_xor_sync(0xffffffffu, red.z, o);
            red.w += __shfl_xor_sync(0xffffffffu, red.w, o);
        }
        if (lane == 0) sred[cur][wid] = red;

        // prefetch must land before the barrier publishes the buffer
        if (j < 63) CP_WAIT0();
        __syncthreads();                      // single barrier per scan step

        // tree-sum the 8 warp partials (depth 3)
        float4 t01 = add4(sred[cur][0], sred[cur][1]);
        float4 t23 = add4(sred[cur][2], sred[cur][3]);
        float4 t45 = add4(sred[cur][4], sred[cur][5]);
        float4 t67 = add4(sred[cur][6], sred[cur][7]);
        float4 tt  = add4(add4(t01, t23), add4(t45, t67));

        float2 s0 = step_scalars(tt.x, tt.y, P0, a2_0);
        float2 s1 = step_scalars(tt.z, tt.w, P1, a2_1);
        P0 *= s0.x;  float qc0 = s0.y * frcp(P0);
        P1 *= s1.x;  float qc1 = s1.y * frcp(P1);
        u64 QC0 = pk(qc0, qc0), QC1 = pk(qc1, qc1);
        #pragma unroll
        for (int i = 0; i < 8; i++) {
            q0a[i] = fma2(QC0, v0[i], q0a[i]);
            q1a[i] = fma2(QC1, v1[i], q1a[i]);
        }
    }

    // ---- epilogue: mobius bias add + project (acc = P*q) ----
    float sa0 = 0.0f, sa1 = 0.0f;
    #pragma unroll
    for (int i = 0; i < 8; i++) {
        float2 p0 = unpk(q0a[i]); sa0 += p0.x + p0.y;
        float2 p1 = unpk(q1a[i]); sa1 += p1.x + p1.y;
    }
    #pragma unroll
    for (int o = 16; o > 0; o >>= 1) {
        sa0 += __shfl_xor_sync(0xffffffffu, sa0, o);
        sa1 += __shfl_xor_sync(0xffffffffu, sa1, o);
    }
    if (lane == 0) sred[0][wid] = make_float4(sa0, sa1, 0.f, 0.f);
    __syncthreads();
    float4 e01 = add4(sred[0][0], sred[0][1]);
    float4 e23 = add4(sred[0][2], sred[0][3]);
    float4 e45 = add4(sred[0][4], sred[0][5]);
    float4 e67 = add4(sred[0][6], sred[0][7]);
    float4 et  = add4(add4(e01, e23), add4(e45, e67));
    float t0 = et.x, t1 = et.y;
    float2 f0 = final_scalars(P0 * t0, a2_0, g_bh[c0]);
    float2 f1 = final_scalars(P1 * t1, a2_1, g_bh[c0 + 1]);
    float fx0 = f0.x * P0, fx1 = f1.x * P1;
    u64 FA0 = pk(fx0, fx0), FB0 = pk(f0.y, f0.y);
    u64 FA1 = pk(fx1, fx1), FB1 = pk(f1.y, f1.y);

    u64* o0 = (u64*)(out + ((size_t)(b * 128 + c0)) * 4096);
    u64* o1 = o0 + 2048;
    #pragma unroll
    for (int orow = 0; orow < 4; orow++) {
        #pragma unroll
        for (int p = 0; p < 2; p++) {
            int pos = (4 * ty + orow) * 32 + 2 * tx + p;   // in float2 units
            o0[pos] = fma2(FA0, q0a[orow * 2 + p], FB0);
            o1[pos] = fma2(FA1, q1a[orow * 2 + p], FB1);
        }
    }
}

// ---------------------------------------------------------------------------
extern "C" void kernel_launch(void* const* d_in, const int* in_sizes, int n_in,
                              void* d_out, int out_size) {
    const float* x    = (const float*)d_in[0];   // [32,64,64,64]
    const float* wgt  = (const float*)d_in[1];   // [128,64,3,3]
    const float* bias = (const float*)d_in[2];   // [128]
    float* out = (float*)d_out;                  // [32,128,64,64]

    u_kernel<<<2049, 256>>>(x, bias);            // block 2048 also does bias
    dim3 grid(64, 32);                           // (cout/2, bs)
    main_kernel<<<grid, 256>>>(wgt, out);
}

// round 8
// speedup vs baseline: 1.2488x; 1.0228x over previous
#include <cuda_runtime.h>
#include <math.h>

// Hyperbolic conv constants (must match reference)
#define CC    0.05f
#define SQC   0.22360679774997896f          // sqrt(0.05)
#define MINN  1e-15f
#define MAXN  (0.996f / SQC)                // (1 - 4e-3)/sqrt(c)
#define MAXN2 (MAXN * MAXN)

typedef unsigned long long u64;

// u tile stride padded to 68 floats (272B = 17*16B) so every row is 16B aligned
#define TW    68
#define TSZ   (66 * TW)                     // 4488 floats per tile
#define TSZ4  (TSZ / 4)                     // 1122 float4

// Scratch: u = logmap0(pad(x)), [b][j][66*68], 32*64*4488 floats (~36.8MB)
__device__ float g_u[9191424];
__device__ float g_bh[128];                 // expmap0(bias)

// ---------------------------------------------------------------------------
// packed f32x2 + fast-approx + cp.async helpers
// ---------------------------------------------------------------------------
__device__ __forceinline__ u64 pk(float a, float b) {
    u64 r;
    asm("mov.b64 %0, {%1, %2};" : "=l"(r)
        : "r"(__float_as_uint(a)), "r"(__float_as_uint(b)));
    return r;
}
__device__ __forceinline__ float2 unpk(u64 v) {
    unsigned lo, hi;
    asm("mov.b64 {%0, %1}, %2;" : "=r"(lo), "=r"(hi) : "l"(v));
    return make_float2(__uint_as_float(lo), __uint_as_float(hi));
}
__device__ __forceinline__ u64 fma2(u64 a, u64 b, u64 c) {
    u64 d;
    asm("fma.rn.f32x2 %0, %1, %2, %3;" : "=l"(d) : "l"(a), "l"(b), "l"(c));
    return d;
}
__device__ __forceinline__ float fexp2(float x){ float r; asm("ex2.approx.f32 %0, %1;" : "=f"(r) : "f"(x)); return r; }
__device__ __forceinline__ float frcp (float x){ float r; asm("rcp.approx.f32 %0, %1;" : "=f"(r) : "f"(x)); return r; }
__device__ __forceinline__ float frsq (float x){ float r; asm("rsqrt.approx.f32 %0, %1;" : "=f"(r) : "f"(x)); return r; }

__device__ __forceinline__ void cpasync16(unsigned saddr, const void* g) {
    asm volatile("cp.async.cg.shared.global [%0], [%1], 16;" :: "r"(saddr), "l"(g));
}
#define CP_COMMIT() asm volatile("cp.async.commit_group;")
#define CP_WAIT0()  asm volatile("cp.async.wait_group 0;")

__device__ __forceinline__ float4 add4(float4 a, float4 b) {
    return make_float4(a.x + b.x, a.y + b.y, a.z + b.z, a.w + b.w);
}

__device__ __forceinline__ float artanhc(float z) {
    z = fminf(z, 1.0f - 1e-7f);             // z >= 0 always here
    return 0.5f * (log1pf(z) - log1pf(-z));
}

// ---------------------------------------------------------------------------
// Kernel 1: u = logmap0(pad(x)) per (b, cin) row (precise), stride-68 layout.
// Block 2048 additionally computes b_h = expmap0(bias).
// ---------------------------------------------------------------------------
__global__ __launch_bounds__(256) void u_kernel(const float* __restrict__ x,
                                                const float* __restrict__ bias) {
    int row = blockIdx.x;
    int t = threadIdx.x;

    if (row == 2048) {                      // bias block
        if (t < 128) {
            float v = bias[t];
            float p = v * v;
            #pragma unroll
            for (int o = 16; o > 0; o >>= 1) p += __shfl_xor_sync(0xffffffffu, p, o);
            __shared__ float smb[4];
            if ((t & 31) == 0) smb[t >> 5] = p;
            __syncwarp();
            asm volatile("bar.sync 1, 128;");
            float s2 = smb[0] + smb[1] + smb[2] + smb[3];
            float bn = fmaxf(sqrtf(s2), MINN);
            float z  = SQC * bn;
            g_bh[t] = tanhf(z) / z * v;
        }
        return;
    }

    const float* xr = x + (size_t)row * 4096;

    float p = 0.0f;
    #pragma unroll
    for (int k = 0; k < 16; k++) { float v = xr[t + (k << 8)]; p += v * v; }
    #pragma unroll
    for (int o = 16; o > 0; o >>= 1) p += __shfl_xor_sync(0xffffffffu, p, o);
    __shared__ float sm[8];
    __shared__ float s_scale;
    if ((t & 31) == 0) sm[t >> 5] = p;
    __syncthreads();
    if (t == 0) {
        float s2 = 0.0f;
        #pragma unroll
        for (int i = 0; i < 8; i++) s2 += sm[i];
        float yn = fmaxf(sqrtf(s2), MINN);
        float z  = SQC * yn;
        s_scale  = artanhc(z) / z;
    }
    __syncthreads();
    float sc = s_scale;

    float* ur = g_u + (size_t)row * TSZ;
    for (int idx = t; idx < TSZ; idx += 256) {
        int r = idx / TW, c = idx - r * TW;
        float v = 0.0f;
        if (r >= 1 && r <= 64 && c >= 1 && c <= 64)
            v = xr[(r - 1) * 64 + (c - 1)] * sc;
        ur[idx] = v;
    }
}

// ---------------------------------------------------------------------------
// Mobius scan scalar math — SHORT CHAIN version.
// Common path needs NO sqrt and only one frcp: the small-z tanh Taylor works
// directly on z^2 = C*|v|^2, and both projection tests compare squared norms.
// Rare branches (uniform across the CTA) preserve exactness for general data.
// acc = P*q;  qv = <q,v>.  Returns (sA, sBt); updates a2 = |acc'|^2.
// ---------------------------------------------------------------------------
__device__ __forceinline__ float2 step_scalars(float sv2, float qv, float P, float& a2) {
    float z2 = CC * sv2;                           // z^2
    float tau;
    if (z2 < 0.0625f) {                            // z < 0.25 (always, this data)
        tau = 1.0f + z2 * (-0.33333334f + z2 * (0.13333334f - z2 * 0.053968254f));
    } else {
        float vn = sv2 * frsq(fmaxf(sv2, 1e-28f));
        float z  = SQC * vn;
        float t  = fexp2(z * 2.8853901f);          // e^{2z}
        tau = (t - 1.0f) * frcp((t + 1.0f) * z);
    }
    float tn2 = tau * tau * sv2;                   // |t|^2 before project
    float ts  = tau;
    if (tn2 > MAXN2) ts = tau * (MAXN * frsq(tn2));  // project(t), rare
    float y2  = ts * ts * sv2;
    float xy  = ts * (P * qv);
    float x2  = a2;
    float A   = 1.0f + 2.0f * CC * xy + CC * y2;
    float B   = 1.0f - CC * x2;
    float den = fmaxf(1.0f + 2.0f * CC * xy + CC * CC * x2 * y2, MINN);
    float inv = frcp(den);
    float n2  = (A * A * x2 + 2.0f * A * B * xy + B * B * y2) * (inv * inv);
    float ps  = 1.0f;
    if (n2 > MAXN2) ps = MAXN * frsq(fmaxf(n2, 1e-28f));  // project(acc'), rare
    a2 = ps * ps * n2;
    return make_float2(A * inv * ps, B * inv * ps * ts);
}

__device__ __forceinline__ float2 final_scalars(float sacc, float a2, float bh) {
    float y2  = 4096.0f * bh * bh;
    float xy  = bh * sacc;
    float x2  = a2;
    float A   = 1.0f + 2.0f * CC * xy + CC * y2;
    float B   = 1.0f - CC * x2;
    float den = fmaxf(1.0f + 2.0f * CC * xy + CC * CC * x2 * y2, MINN);
    float inv = frcp(den);
    float n2  = (A * A * x2 + 2.0f * A * B * xy + B * B * y2) * (inv * inv);
    float ps  = 1.0f;
    if (n2 > MAXN2) ps = MAXN * frsq(fmaxf(n2, 1e-28f));
    return make_float2(A * inv * ps, B * inv * ps * bh);
}

// load one 6-wide window row (16B-aligned) as 5 overlapping f32x2 pairs
__device__ __forceinline__ void loadrow(const float* p, u64* row) {
    float4 a = *(const float4*)p;           // floats 0-3 (LDS.128)
    float2 b = *(const float2*)(p + 4);     // floats 4-5 (LDS.64)
    row[0] = pk(a.x, a.y);
    row[1] = pk(a.y, a.z);
    row[2] = pk(a.z, a.w);
    row[3] = pk(a.w, b.x);
    row[4] = pk(b.x, b.y);
}

// ---------------------------------------------------------------------------
// Kernel 2: one CTA per (b, channel pair). 256 threads, 4x4 outputs each,
// columns packed f32x2. Double-buffered tile via cp.async (branchless wrap),
// single barrier per scan step, short redundant scalar chain per thread.
// ---------------------------------------------------------------------------
__global__ __launch_bounds__(256, 2)
void main_kernel(const float* __restrict__ w, float* __restrict__ out) {
    const int b    = blockIdx.y;
    const int c0   = blockIdx.x * 2;
    const int tid  = threadIdx.x;
    const int ty   = tid >> 4;
    const int tx   = tid & 15;
    const int lane = tid & 31;
    const int wid  = tid >> 5;

    __shared__ float  su[2 * TSZ];      // double-buffered 66x68 tile
    __shared__ u64    swp[2][576];      // weights pre-duplicated (w,w)
    __shared__ float4 sred[2][8];

    for (int i = tid; i < 1152; i += 256) {
        int cc = i / 576, rem = i - cc * 576;
        float wv = w[(size_t)(c0 + cc) * 576 + rem];
        swp[cc][rem] = pk(wv, wv);
    }

    const unsigned su_s = (unsigned)__cvta_generic_to_shared(su);
    const float4* gbase = (const float4*)(g_u + (size_t)(b * 64) * TSZ);
    const int tail = tid + 1024;            // only first 98 threads copy chunk 5

    // preload tile 0 into buf0 via cp.async
    #pragma unroll
    for (int k = 0; k < 4; k++) {
        int i = tid + (k << 8);
        cpasync16(su_s + i * 16, gbase + i);
    }
    if (tail < TSZ4) cpasync16(su_s + tail * 16, gbase + tail);
    CP_COMMIT();
    CP_WAIT0();
    __syncthreads();

    u64 q0a[8], q1a[8];                 // acc = P * q, packed col pairs
    #pragma unroll
    for (int i = 0; i < 8; i++) { q0a[i] = 0ull; q1a[i] = 0ull; }
    float a2_0 = 0.0f, a2_1 = 0.0f, P0 = 1.0f, P1 = 1.0f;

    const int baseoff = (4 * ty) * TW + 4 * tx;

    #pragma unroll 2
    for (int j = 0; j < 64; j++) {
        const int cur = j & 1;

        // ---- branchless async prefetch of tile (j+1)&63 into other buffer ----
        {
            const float4* gn = gbase + (size_t)((j + 1) & 63) * TSZ4;
            unsigned sn = su_s + (cur ^ 1) * (TSZ * 4);
            #pragma unroll
            for (int k = 0; k < 4; k++) {
                int i = tid + (k << 8);
                cpasync16(sn + i * 16, gn + i);
            }
            if (tail < TSZ4) cpasync16(sn + tail * 16, gn + tail);
            CP_COMMIT();
        }

        const float* basep = su + cur * TSZ + baseoff;
        const u64* wp0 = &swp[0][j * 9];
        const u64* wp1 = &swp[1][j * 9];

        // ---- conv: rolling 3-row window; weights broadcast from smem ----
        u64 v0[8], v1[8];
        u64 rwin[3][5];
        #pragma unroll
        for (int r = 0; r < 3; r++) loadrow(basep + r * TW, rwin[r]);

        #pragma unroll
        for (int orow = 0; orow < 4; orow++) {
            u64 s00 = 0ull, s01 = 0ull, s10 = 0ull, s11 = 0ull;
            #pragma unroll
            for (int r = 0; r < 3; r++) {
                const u64* rw = rwin[(orow + r) % 3];
                #pragma unroll
                for (int k = 0; k < 3; k++) {
                    u64 wa = wp0[r * 3 + k];
                    u64 wb = wp1[r * 3 + k];
                    s00 = fma2(rw[k],     wa, s00);
                    s01 = fma2(rw[2 + k], wa, s01);
                    s10 = fma2(rw[k],     wb, s10);
                    s11 = fma2(rw[2 + k], wb, s11);
                }
            }
            v0[orow * 2]     = s00;
            v0[orow * 2 + 1] = s01;
            v1[orow * 2]     = s10;
            v1[orow * 2 + 1] = s11;
            if (orow < 3) loadrow(basep + (orow + 3) * TW, rwin[orow % 3]);
        }

        // ---- fused packed reduction: |v|^2 and <q,v> per channel ----
        u64 sq0 = 0ull, av0 = 0ull, sq1 = 0ull, av1 = 0ull;
        #pragma unroll
        for (int i = 0; i < 8; i++) {
            sq0 = fma2(v0[i], v0[i], sq0);
            av0 = fma2(q0a[i], v0[i], av0);
            sq1 = fma2(v1[i], v1[i], sq1);
            av1 = fma2(q1a[i], v1[i], av1);
        }
        float2 pa = unpk(sq0), pb = unpk(av0), pc = unpk(sq1), pd = unpk(av1);
        float4 red = make_float4(pa.x + pa.y, pb.x + pb.y, pc.x + pc.y, pd.x + pd.y);
        #pragma unroll
        for (int o = 16; o > 0; o >>= 1) {
            red.x += __shfl_xor_sync(0xffffffffu, red.x, o);
            red.y += __shfl_xor_sync(0xffffffffu, red.y, o);
            red.z += __shfl_xor_sync(0xffffffffu, red.z, o);
            red.w += __shfl_xor_sync(0xffffffffu, red.w, o);
        }
        if (lane == 0) sred[cur][wid] = red;

        // prefetch must land before the barrier publishes the buffer
        CP_WAIT0();
        __syncthreads();                      // single barrier per scan step

        // tree-sum the 8 warp partials (depth 3)
        float4 t01 = add4(sred[cur][0], sred[cur][1]);
        float4 t23 = add4(sred[cur][2], sred[cur][3]);
        float4 t45 = add4(sred[cur][4], sred[cur][5]);
        float4 t67 = add4(sred[cur][6], sred[cur][7]);
        float4 tt  = add4(add4(t01, t23), add4(t45, t67));

        float2 s0 = step_scalars(tt.x, tt.y, P0, a2_0);
        float2 s1 = step_scalars(tt.z, tt.w, P1, a2_1);
        P0 *= s0.x;  float qc0 = s0.y * frcp(P0);
        P1 *= s1.x;  float qc1 = s1.y * frcp(P1);
        u64 QC0 = pk(qc0, qc0), QC1 = pk(qc1, qc1);
        #pragma unroll
        for (int i = 0; i < 8; i++) {
            q0a[i] = fma2(QC0, v0[i], q0a[i]);
            q1a[i] = fma2(QC1, v1[i], q1a[i]);
        }
    }

    // ---- epilogue: mobius bias add + project (acc = P*q) ----
    float sa0 = 0.0f, sa1 = 0.0f;
    #pragma unroll
    for (int i = 0; i < 8; i++) {
        float2 p0 = unpk(q0a[i]); sa0 += p0.x + p0.y;
        float2 p1 = unpk(q1a[i]); sa1 += p1.x + p1.y;
    }
    #pragma unroll
    for (int o = 16; o > 0; o >>= 1) {
        sa0 += __shfl_xor_sync(0xffffffffu, sa0, o);
        sa1 += __shfl_xor_sync(0xffffffffu, sa1, o);
    }
    if (lane == 0) sred[0][wid] = make_float4(sa0, sa1, 0.f, 0.f);
    __syncthreads();
    float4 e01 = add4(sred[0][0], sred[0][1]);
    float4 e23 = add4(sred[0][2], sred[0][3]);
    float4 e45 = add4(sred[0][4], sred[0][5]);
    float4 e67 = add4(sred[0][6], sred[0][7]);
    float4 et  = add4(add4(e01, e23), add4(e45, e67));
    float t0 = et.x, t1 = et.y;
    float2 f0 = final_scalars(P0 * t0, a2_0, g_bh[c0]);
    float2 f1 = final_scalars(P1 * t1, a2_1, g_bh[c0 + 1]);
    float fx0 = f0.x * P0, fx1 = f1.x * P1;
    u64 FA0 = pk(fx0, fx0), FB0 = pk(f0.y, f0.y);
    u64 FA1 = pk(fx1, fx1), FB1 = pk(f1.y, f1.y);

    u64* o0 = (u64*)(out + ((size_t)(b * 128 + c0)) * 4096);
    u64* o1 = o0 + 2048;
    #pragma unroll
    for (int orow = 0; orow < 4; orow++) {
        #pragma unroll
        for (int p = 0; p < 2; p++) {
            int pos = (4 * ty + orow) * 32 + 2 * tx + p;   // in float2 units
            o0[pos] = fma2(FA0, q0a[orow * 2 + p], FB0);
            o1[pos] = fma2(FA1, q1a[orow * 2 + p], FB1);
        }
    }
}

// ---------------------------------------------------------------------------
extern "C" void kernel_launch(void* const* d_in, const int* in_sizes, int n_in,
                              void* d_out, int out_size) {
    const float* x    = (const float*)d_in[0];   // [32,64,64,64]
    const float* wgt  = (const float*)d_in[1];   // [128,64,3,3]
    const float* bias = (const float*)d_in[2];   // [128]
    float* out = (float*)d_out;                  // [32,128,64,64]

    u_kernel<<<2049, 256>>>(x, bias);            // block 2048 also does bias
    dim3 grid(64, 32);                           // (cout/2, bs)
    main_kernel<<<grid, 256>>>(wgt, out);
}

// round 10
// speedup vs baseline: 1.3987x; 1.1200x over previous
#include <cuda_runtime.h>
#include <math.h>

// Hyperbolic conv constants (must match reference)
#define CC    0.05f
#define SQC   0.22360679774997896f          // sqrt(0.05)
#define MINN  1e-15f
#define MAXN  (0.996f / SQC)                // (1 - 4e-3)/sqrt(c)
#define MAXN2 (MAXN * MAXN)

typedef unsigned long long u64;

// u tile stride padded to 68 floats (272B = 17*16B) so every row is 16B aligned
#define TW    68
#define TSZ   (66 * TW)                     // 4488 floats per tile
#define TSZ4  (TSZ / 4)                     // 1122 float4

// Scratch: u = logmap0(pad(x)), [b][j][66*68], 32*64*4488 floats (~36.8MB)
__device__ float g_u[9191424];
__device__ float g_bh[128];                 // expmap0(bias)

// ---------------------------------------------------------------------------
// packed f32x2 + fast-approx + cp.async helpers
// ---------------------------------------------------------------------------
__device__ __forceinline__ u64 pk(float a, float b) {
    u64 r;
    asm("mov.b64 %0, {%1, %2};" : "=l"(r)
        : "r"(__float_as_uint(a)), "r"(__float_as_uint(b)));
    return r;
}
__device__ __forceinline__ float2 unpk(u64 v) {
    unsigned lo, hi;
    asm("mov.b64 {%0, %1}, %2;" : "=r"(lo), "=r"(hi) : "l"(v));
    return make_float2(__uint_as_float(lo), __uint_as_float(hi));
}
__device__ __forceinline__ u64 fma2(u64 a, u64 b, u64 c) {
    u64 d;
    asm("fma.rn.f32x2 %0, %1, %2, %3;" : "=l"(d) : "l"(a), "l"(b), "l"(c));
    return d;
}
__device__ __forceinline__ float fexp2(float x){ float r; asm("ex2.approx.f32 %0, %1;" : "=f"(r) : "f"(x)); return r; }
__device__ __forceinline__ float frcp (float x){ float r; asm("rcp.approx.f32 %0, %1;" : "=f"(r) : "f"(x)); return r; }
__device__ __forceinline__ float frsq (float x){ float r; asm("rsqrt.approx.f32 %0, %1;" : "=f"(r) : "f"(x)); return r; }

__device__ __forceinline__ void cpasync16(unsigned saddr, const void* g) {
    asm volatile("cp.async.cg.shared.global [%0], [%1], 16;" :: "r"(saddr), "l"(g));
}
#define CP_COMMIT() asm volatile("cp.async.commit_group;")
#define CP_WAIT0()  asm volatile("cp.async.wait_group 0;")

__device__ __forceinline__ float artanhc(float z) {
    z = fminf(z, 1.0f - 1e-7f);             // z >= 0 always here
    return 0.5f * (log1pf(z) - log1pf(-z));
}

// ---------------------------------------------------------------------------
// Kernel 1: u = logmap0(pad(x)) per (b, cin) row (precise), stride-68 layout.
// Block 2048 additionally computes b_h = expmap0(bias).
// ---------------------------------------------------------------------------
__global__ __launch_bounds__(256) void u_kernel(const float* __restrict__ x,
                                                const float* __restrict__ bias) {
    int row = blockIdx.x;
    int t = threadIdx.x;

    if (row == 2048) {                      // bias block
        if (t < 128) {
            float v = bias[t];
            float p = v * v;
            #pragma unroll
            for (int o = 16; o > 0; o >>= 1) p += __shfl_xor_sync(0xffffffffu, p, o);
            __shared__ float smb[4];
            if ((t & 31) == 0) smb[t >> 5] = p;
            __syncwarp();
            asm volatile("bar.sync 1, 128;");
            float s2 = smb[0] + smb[1] + smb[2] + smb[3];
            float bn = fmaxf(sqrtf(s2), MINN);
            float z  = SQC * bn;
            g_bh[t] = tanhf(z) / z * v;
        }
        return;
    }

    const float* xr = x + (size_t)row * 4096;

    float p = 0.0f;
    #pragma unroll
    for (int k = 0; k < 16; k++) { float v = xr[t + (k << 8)]; p += v * v; }
    #pragma unroll
    for (int o = 16; o > 0; o >>= 1) p += __shfl_xor_sync(0xffffffffu, p, o);
    __shared__ float sm[8];
    __shared__ float s_scale;
    if ((t & 31) == 0) sm[t >> 5] = p;
    __syncthreads();
    if (t == 0) {
        float s2 = 0.0f;
        #pragma unroll
        for (int i = 0; i < 8; i++) s2 += sm[i];
        float yn = fmaxf(sqrtf(s2), MINN);
        float z  = SQC * yn;
        s_scale  = artanhc(z) / z;
    }
    __syncthreads();
    float sc = s_scale;

    float* ur = g_u + (size_t)row * TSZ;
    for (int idx = t; idx < TSZ; idx += 256) {
        int r = idx / TW, c = idx - r * TW;
        float v = 0.0f;
        if (r >= 1 && r <= 64 && c >= 1 && c <= 64)
            v = xr[(r - 1) * 64 + (c - 1)] * sc;
        ur[idx] = v;
    }
}

// ---------------------------------------------------------------------------
// Mobius scan scalar math — short chain (no sqrt on common path).
// acc = P*q;  qv = <q,v>.  Returns (sA, sBt); updates a2 = |acc'|^2.
// ---------------------------------------------------------------------------
__device__ __forceinline__ float2 step_scalars(float sv2, float qv, float P, float& a2) {
    float z2 = CC * sv2;                           // z^2
    float tau;
    if (z2 < 0.0625f) {                            // z < 0.25 (always, this data)
        tau = 1.0f + z2 * (-0.33333334f + z2 * (0.13333334f - z2 * 0.053968254f));
    } else {
        float vn = sv2 * frsq(fmaxf(sv2, 1e-28f));
        float z  = SQC * vn;
        float t  = fexp2(z * 2.8853901f);          // e^{2z}
        tau = (t - 1.0f) * frcp((t + 1.0f) * z);
    }
    float tn2 = tau * tau * sv2;                   // |t|^2 before project
    float ts  = tau;
    if (tn2 > MAXN2) ts = tau * (MAXN * frsq(tn2));  // project(t), rare
    float y2  = ts * ts * sv2;
    float xy  = ts * (P * qv);
    float x2  = a2;
    float A   = 1.0f + 2.0f * CC * xy + CC * y2;
    float B   = 1.0f - CC * x2;
    float den = fmaxf(1.0f + 2.0f * CC * xy + CC * CC * x2 * y2, MINN);
    float inv = frcp(den);
    float n2  = (A * A * x2 + 2.0f * A * B * xy + B * B * y2) * (inv * inv);
    float ps  = 1.0f;
    if (n2 > MAXN2) ps = MAXN * frsq(fmaxf(n2, 1e-28f));  // project(acc'), rare
    a2 = ps * ps * n2;
    return make_float2(A * inv * ps, B * inv * ps * ts);
}

__device__ __forceinline__ float2 final_scalars(float sacc, float a2, float bh) {
    float y2  = 4096.0f * bh * bh;
    float xy  = bh * sacc;
    float x2  = a2;
    float A   = 1.0f + 2.0f * CC * xy + CC * y2;
    float B   = 1.0f - CC * x2;
    float den = fmaxf(1.0f + 2.0f * CC * xy + CC * CC * x2 * y2, MINN);
    float inv = frcp(den);
    float n2  = (A * A * x2 + 2.0f * A * B * xy + B * B * y2) * (inv * inv);
    float ps  = 1.0f;
    if (n2 > MAXN2) ps = MAXN * frsq(fmaxf(n2, 1e-28f));
    return make_float2(A * inv * ps, B * inv * ps * bh);
}

// load one 6-wide window row (16B-aligned) as 5 overlapping f32x2 pairs
__device__ __forceinline__ void loadrow(const float* p, u64* row) {
    float4 a = *(const float4*)p;           // floats 0-3 (LDS.128)
    float2 b = *(const float2*)(p + 4);     // floats 4-5 (LDS.64)
    row[0] = pk(a.x, a.y);
    row[1] = pk(a.y, a.z);
    row[2] = pk(a.z, a.w);
    row[3] = pk(a.w, b.x);
    row[4] = pk(b.x, b.y);
}

// ---------------------------------------------------------------------------
// Kernel 2: one CTA per (b, channel pair). 256 threads, 4x4 outputs each,
// columns packed f32x2. cp.async double buffer, one barrier per scan step.
// Parity-split butterfly (10 SHFL/iter) feeds lane-parity Mobius chains.
// ---------------------------------------------------------------------------
__global__ __launch_bounds__(256, 2)
void main_kernel(const float* __restrict__ w, float* __restrict__ out) {
    const int b    = blockIdx.y;
    const int c0   = blockIdx.x * 2;
    const int tid  = threadIdx.x;
    const int ty   = tid >> 4;
    const int tx   = tid & 15;
    const int lane = tid & 31;
    const int wid  = tid >> 5;
    const int par  = lane & 1;          // my scalar-chain channel (0 or 1)

    __shared__ float  su[2 * TSZ];      // double-buffered 66x68 tile
    __shared__ u64    swp[2][576];      // weights pre-duplicated (w,w)
    __shared__ float2 sred[2][16];      // [buf][wid*2 + parity]

    for (int i = tid; i < 1152; i += 256) {
        int cc = i / 576, rem = i - cc * 576;
        float wv = w[(size_t)(c0 + cc) * 576 + rem];
        swp[cc][rem] = pk(wv, wv);
    }

    const unsigned su_s = (unsigned)__cvta_generic_to_shared(su);
    const float4* gbase = (const float4*)(g_u + (size_t)(b * 64) * TSZ);
    const int tail = tid + 1024;            // only first 98 threads copy chunk 5

    // preload tile 0 into buf0 via cp.async
    #pragma unroll
    for (int k = 0; k < 4; k++) {
        int i = tid + (k << 8);
        cpasync16(su_s + i * 16, gbase + i);
    }
    if (tail < TSZ4) cpasync16(su_s + tail * 16, gbase + tail);
    CP_COMMIT();
    CP_WAIT0();
    __syncthreads();

    u64 q0a[8], q1a[8];                 // acc = P * q, packed col pairs
    #pragma unroll
    for (int i = 0; i < 8; i++) { q0a[i] = 0ull; q1a[i] = 0ull; }
    float a2m = 0.0f, Pm = 1.0f;        // per-lane: channel `par`'s scan state

    const int baseoff = (4 * ty) * TW + 4 * tx;

    #pragma unroll 2
    for (int j = 0; j < 64; j++) {
        const int cur = j & 1;

        // ---- branchless async prefetch of tile (j+1)&63 into other buffer ----
        {
            const float4* gn = gbase + (size_t)((j + 1) & 63) * TSZ4;
            unsigned sn = su_s + (cur ^ 1) * (TSZ * 4);
            #pragma unroll
            for (int k = 0; k < 4; k++) {
                int i = tid + (k << 8);
                cpasync16(sn + i * 16, gn + i);
            }
            if (tail < TSZ4) cpasync16(sn + tail * 16, gn + tail);
            CP_COMMIT();
        }

        const float* basep = su + cur * TSZ + baseoff;
        const u64* wp0 = &swp[0][j * 9];
        const u64* wp1 = &swp[1][j * 9];

        // ---- conv: rolling 3-row window; weights broadcast from smem ----
        u64 v0[8], v1[8];
        u64 rwin[3][5];
        #pragma unroll
        for (int r = 0; r < 3; r++) loadrow(basep + r * TW, rwin[r]);

        #pragma unroll
        for (int orow = 0; orow < 4; orow++) {
            u64 s00 = 0ull, s01 = 0ull, s10 = 0ull, s11 = 0ull;
            #pragma unroll
            for (int r = 0; r < 3; r++) {
                const u64* rw = rwin[(orow + r) % 3];
                #pragma unroll
                for (int k = 0; k < 3; k++) {
                    u64 wa = wp0[r * 3 + k];
                    u64 wb = wp1[r * 3 + k];
                    s00 = fma2(rw[k],     wa, s00);
                    s01 = fma2(rw[2 + k], wa, s01);
                    s10 = fma2(rw[k],     wb, s10);
                    s11 = fma2(rw[2 + k], wb, s11);
                }
            }
            v0[orow * 2]     = s00;
            v0[orow * 2 + 1] = s01;
            v1[orow * 2]     = s10;
            v1[orow * 2 + 1] = s11;
            if (orow < 3) loadrow(basep + (orow + 3) * TW, rwin[orow % 3]);
        }

        // ---- fused packed reduction: |v|^2 and <q,v> per channel ----
        u64 sq0 = 0ull, av0 = 0ull, sq1 = 0ull, av1 = 0ull;
        #pragma unroll
        for (int i = 0; i < 8; i++) {
            sq0 = fma2(v0[i], v0[i], sq0);
            av0 = fma2(q0a[i], v0[i], av0);
            sq1 = fma2(v1[i], v1[i], sq1);
            av1 = fma2(q1a[i], v1[i], av1);
        }
        float2 pa = unpk(sq0), pb = unpk(av0), pc = unpk(sq1), pd = unpk(av1);
        float s0p = pa.x + pa.y, d0p = pb.x + pb.y;   // ch0 partials
        float s1p = pc.x + pc.y, d1p = pd.x + pd.y;   // ch1 partials

        // ---- parity-split butterfly: even lanes own ch0, odd lanes ch1 ----
        float s_mine = par ? s1p : s0p;
        float d_mine = par ? d1p : d0p;
        float s_oth  = par ? s0p : s1p;
        float d_oth  = par ? d0p : d1p;
        s_mine += __shfl_xor_sync(0xffffffffu, s_oth, 1);
        d_mine += __shfl_xor_sync(0xffffffffu, d_oth, 1);
        #pragma unroll
        for (int o = 2; o <= 16; o <<= 1) {
            s_mine += __shfl_xor_sync(0xffffffffu, s_mine, o);
            d_mine += __shfl_xor_sync(0xffffffffu, d_mine, o);
        }
        if (lane < 2) sred[cur][wid * 2 + par] = make_float2(s_mine, d_mine);

        // prefetch must land before the barrier publishes the buffer
        CP_WAIT0();
        __syncthreads();                      // single barrier per scan step

        // tree-sum the 8 warp partials of MY parity (float2, broadcast reads)
        float2 r0 = sred[cur][0 * 2 + par], r1 = sred[cur][1 * 2 + par];
        float2 r2 = sred[cur][2 * 2 + par], r3 = sred[cur][3 * 2 + par];
        float2 r4 = sred[cur][4 * 2 + par], r5 = sred[cur][5 * 2 + par];
        float2 r6 = sred[cur][6 * 2 + par], r7 = sred[cur][7 * 2 + par];
        float sv2 = ((r0.x + r1.x) + (r2.x + r3.x)) + ((r4.x + r5.x) + (r6.x + r7.x));
        float qv  = ((r0.y + r1.y) + (r2.y + r3.y)) + ((r4.y + r5.y) + (r6.y + r7.y));

        // ---- lane-parity scalar chain ----
        float2 s = step_scalars(sv2, qv, Pm, a2m);
        Pm *= s.x;
        float qcm = s.y * frcp(Pm);
        float qc0 = __shfl_sync(0xffffffffu, qcm, 0);
        float qc1 = __shfl_sync(0xffffffffu, qcm, 1);
        u64 QC0 = pk(qc0, qc0), QC1 = pk(qc1, qc1);
        #pragma unroll
        for (int i = 0; i < 8; i++) {
            q0a[i] = fma2(QC0, v0[i], q0a[i]);
            q1a[i] = fma2(QC1, v1[i], q1a[i]);
        }
    }

    // ---- epilogue: mobius bias add + project (acc = P*q) ----
    float sa0 = 0.0f, sa1 = 0.0f;
    #pragma unroll
    for (int i = 0; i < 8; i++) {
        float2 p0 = unpk(q0a[i]); sa0 += p0.x + p0.y;
        float2 p1 = unpk(q1a[i]); sa1 += p1.x + p1.y;
    }
    {
        float m  = par ? sa1 : sa0;
        float ot = par ? sa0 : sa1;
        m += __shfl_xor_sync(0xffffffffu, ot, 1);
        #pragma unroll
        for (int o = 2; o <= 16; o <<= 1)
            m += __shfl_xor_sync(0xffffffffu, m, o);
        if (lane < 2) sred[0][wid * 2 + par] = make_float2(m, 0.f);
    }
    __syncthreads();
    float tm = 0.0f;
    #pragma unroll
    for (int i = 0; i < 8; i++) tm += sred[0][i * 2 + par].x;

    // lane-parity final scalars, then broadcast
    float2 f = final_scalars(Pm * tm, a2m, g_bh[c0 + par]);
    float fxm = f.x * Pm;
    float fa0 = __shfl_sync(0xffffffffu, fxm, 0);
    float fb0 = __shfl_sync(0xffffffffu, f.y, 0);
    float fa1 = __shfl_sync(0xffffffffu, fxm, 1);
    float fb1 = __shfl_sync(0xffffffffu, f.y, 1);
    u64 FA0 = pk(fa0, fa0), FB0 = pk(fb0, fb0);
    u64 FA1 = pk(fa1, fa1), FB1 = pk(fb1, fb1);

    u64* o0 = (u64*)(out + ((size_t)(b * 128 + c0)) * 4096);
    u64* o1 = o0 + 2048;
    #pragma unroll
    for (int orow = 0; orow < 4; orow++) {
        #pragma unroll
        for (int p = 0; p < 2; p++) {
            int pos = (4 * ty + orow) * 32 + 2 * tx + p;   // in float2 units
            o0[pos] = fma2(FA0, q0a[orow * 2 + p], FB0);
            o1[pos] = fma2(FA1, q1a[orow * 2 + p], FB1);
        }
    }
}

// ---------------------------------------------------------------------------
extern "C" void kernel_launch(void* const* d_in, const int* in_sizes, int n_in,
                              void* d_out, int out_size) {
    const float* x    = (const float*)d_in[0];   // [32,64,64,64]
    const float* wgt  = (const float*)d_in[1];   // [128,64,3,3]
    const float* bias = (const float*)d_in[2];   // [128]
    float* out = (float*)d_out;                  // [32,128,64,64]

    u_kernel<<<2049, 256>>>(x, bias);            // block 2048 also does bias
    dim3 grid(64, 32);                           // (cout/2, bs)
    main_kernel<<<grid, 256>>>(wgt, out);
}